// round 1
// baseline (speedup 1.0000x reference)
#include <cuda_runtime.h>
#include <math.h>

// Shapes
// B=8, D=64, O=256 (ope rows after slicing 1:-1), I=256, G=HID=128
// Inputs (metadata order):
// 0 ope_gat (8,258,64) 1 insert_gat (8,256,64) 2 h (8,64) 3 c (8,64)
// 4 W_ih (256,64) 5 W_hh (256,64) 6 b_ih (256) 7 b_hh (256)
// 8 Wv0 (128,64) 9 bv0 (128) 10 Wv1 (128,128) 11 bv1 (128) 12 Wv2 (1,128) 13 bv2 (1)
// 14 Wa0 (128,192) 15 ba0 (128) 16 Wa1 (128,128) 17 ba1 (128) 18 Wa2 (1,128) 19 ba2 (1)
// Output: V(8) | A(8*65536) | hn(8*64) | cn(8*64)  => 525320 floats

#define OFF_V  0
#define OFF_A  8
#define OFF_HN 524296
#define OFF_CN 524808

// ---- scratch (device globals; no allocation allowed) ----
__device__ float g_u[8 * 128];          // per-b constant part (incl. ba1), Wa1-transformed
__device__ float g_M[2 * 128 * 64];     // [0]=Wa1@Wo, [1]=Wa1@Wi  (row-major [g][d])
__device__ float g_c1[128];             // 0.505 * Wa2
__device__ float g_c2[128];             // 0.495 * Wa2
__device__ float g_vv[8 * 256 * 128];   // vv[b,o,g] = M_o . ope + u[b]
__device__ float g_w[8 * 256 * 128];    // w[b,i,g]  = M_i . insert
__device__ float g_PQ[4096];            // [0:2048) P rows (b,o), [2048:4096) Q rows (b,i)

__device__ __forceinline__ float sigm(float x) { return 1.0f / (1.0f + expf(-x)); }

// ============================================================
// K1: per-batch small work: state mean, LSTM cell, V head, t & u
// grid 8, block 256
// ============================================================
__global__ void k_small(const float* __restrict__ ope,
                        const float* __restrict__ h_in,
                        const float* __restrict__ c_in,
                        const float* __restrict__ W_ih,
                        const float* __restrict__ W_hh,
                        const float* __restrict__ b_ih,
                        const float* __restrict__ b_hh,
                        const float* __restrict__ Wv0, const float* __restrict__ bv0,
                        const float* __restrict__ Wv1, const float* __restrict__ bv1,
                        const float* __restrict__ Wv2, const float* __restrict__ bv2,
                        const float* __restrict__ Wa0, const float* __restrict__ ba0,
                        const float* __restrict__ Wa1, const float* __restrict__ ba1,
                        float* __restrict__ out)
{
    __shared__ float s_state[64], s_h[64], s_gates[256], s_hn[64];
    __shared__ float s_z0[128], s_z1[128], s_t[128];
    const int b = blockIdx.x;
    const int t = threadIdx.x;

    if (t < 64) {
        const float* base = ope + (b * 258 + 1) * 64 + t;
        float s = 0.f;
        #pragma unroll 8
        for (int o = 0; o < 256; o++) s += base[o * 64];
        s_state[t] = s * (1.0f / 256.0f);
    } else if (t < 128) {
        s_h[t - 64] = h_in[b * 64 + (t - 64)];
    }
    __syncthreads();

    // gates[t] for all 256 gate outputs
    {
        float acc = b_ih[t] + b_hh[t];
        const float* wi = W_ih + t * 64;
        const float* wh = W_hh + t * 64;
        #pragma unroll 8
        for (int d = 0; d < 64; d++) acc += wi[d] * s_state[d] + wh[d] * s_h[d];
        s_gates[t] = acc;
    }
    __syncthreads();

    if (t < 64) {
        float ig = sigm(s_gates[t]);
        float fg = sigm(s_gates[64 + t]);
        float gg = tanhf(s_gates[128 + t]);
        float og = sigm(s_gates[192 + t]);
        float cn = fg * c_in[b * 64 + t] + ig * gg;
        float hn = og * tanhf(cn);
        s_hn[t] = hn;
        out[OFF_HN + b * 64 + t] = hn;
        out[OFF_CN + b * 64 + t] = cn;
    }
    __syncthreads();

    if (t < 128) {
        // V head layer 0 (NO activation per reference)
        float a = bv0[t];
        const float* w = Wv0 + t * 64;
        #pragma unroll 8
        for (int d = 0; d < 64; d++) a += w[d] * s_hn[d];
        s_z0[t] = a;
    } else {
        // t[g] = Ws @ hn + ba0  (Ws = Wa0[:, 0:64])
        int g = t - 128;
        float a = ba0[g];
        const float* w = Wa0 + g * 192;
        #pragma unroll 8
        for (int d = 0; d < 64; d++) a += w[d] * s_hn[d];
        s_t[g] = a;
    }
    __syncthreads();

    if (t < 128) {
        float a = bv1[t];
        const float* w = Wv1 + t * 128;
        #pragma unroll 8
        for (int d = 0; d < 128; d++) a += w[d] * s_z0[d];
        s_z1[t] = (a >= 0.f) ? a : 0.01f * a;
    } else {
        int g = t - 128;
        float a = ba1[g];
        const float* w = Wa1 + g * 128;
        #pragma unroll 8
        for (int d = 0; d < 128; d++) a += w[d] * s_t[d];
        g_u[b * 128 + g] = a;   // includes ba1
    }
    __syncthreads();

    if (t == 0) {
        float a = bv2[0];
        #pragma unroll 8
        for (int k = 0; k < 128; k++) a += Wv2[k] * s_z1[k];
        out[OFF_V + b] = a;
    }
}

// ============================================================
// K2: M_o = Wa1 @ Wo, M_i = Wa1 @ Wi ; also c1/c2
// grid 64, block 256 (idx over 16384 outputs, K=128)
// ============================================================
__global__ void k_m(const float* __restrict__ Wa0,
                    const float* __restrict__ Wa1,
                    const float* __restrict__ Wa2)
{
    int idx = blockIdx.x * 256 + threadIdx.x;  // 0..16383
    int m = idx >> 13;          // 0: Wo, 1: Wi
    int g = (idx >> 6) & 127;
    int d = idx & 63;
    const float* wa1 = Wa1 + g * 128;
    const float* wa0 = Wa0 + 64 + m * 64 + d;  // column (64 + m*64 + d)
    float acc = 0.f;
    #pragma unroll 8
    for (int h = 0; h < 128; h++) acc += wa1[h] * wa0[h * 192];
    g_M[idx] = acc;

    if (idx < 128) {
        float w2 = Wa2[idx];
        g_c1[idx] = 0.505f * w2;
        g_c2[idx] = 0.495f * w2;
    }
}

// ============================================================
// K3: vv rows (2048) and w rows (2048). 16 rows/block.
// grid 256, block 128 (thread = g). M row held in registers.
// ============================================================
__global__ void __launch_bounds__(128) k_vw(const float* __restrict__ ope,
                                            const float* __restrict__ ins)
{
    __shared__ float sIn[16][64];
    const int rbase = blockIdx.x * 16;
    const int g = threadIdx.x;
    const bool isV = (rbase < 2048);

    // Load this thread's M row (64 floats) into registers
    const float4* Mrow = (const float4*)(g_M + (isV ? 0 : 8192) + g * 64);
    float4 m[16];
    #pragma unroll
    for (int j = 0; j < 16; j++) m[j] = Mrow[j];

    // Stage 16 input rows
    for (int l = threadIdx.x; l < 1024; l += 128) {
        int r = l >> 6, d = l & 63;
        int row = rbase + r;
        const float* src;
        if (row < 2048) {
            int b = row >> 8, o = row & 255;
            src = ope + (b * 258 + (o + 1)) * 64;
        } else {
            int rr = row - 2048;
            int b = rr >> 8, i = rr & 255;
            src = ins + (b * 256 + i) * 64;
        }
        sIn[r][d] = src[d];
    }
    __syncthreads();

    #pragma unroll 4
    for (int r = 0; r < 16; r++) {
        int row = rbase + r;
        float acc = isV ? g_u[(row >> 8) * 128 + g] : 0.0f;
        const float4* ip = (const float4*)(&sIn[r][0]);
        #pragma unroll
        for (int j = 0; j < 16; j++) {
            float4 x = ip[j];  // broadcast across the warp
            acc += m[j].x * x.x + m[j].y * x.y + m[j].z * x.z + m[j].w * x.w;
        }
        if (isV) g_vv[row * 128 + g] = acc;
        else     g_w[(row - 2048) * 128 + g] = acc;
    }
}

// ============================================================
// K4: P[row] = c1 . row  for all 4096 rows (vv then w)
// grid 512, block 256 (one warp per row)
// ============================================================
__global__ void k_pq()
{
    int warp = threadIdx.x >> 5, lane = threadIdx.x & 31;
    int row = blockIdx.x * 8 + warp;  // 0..4095
    const float* src = (row < 2048) ? (g_vv + row * 128) : (g_w + (row - 2048) * 128);
    float4 v = ((const float4*)src)[lane];
    float4 cc = ((const float4*)g_c1)[lane];
    float s = v.x * cc.x + v.y * cc.y + v.z * cc.z + v.w * cc.w;
    #pragma unroll
    for (int off = 16; off; off >>= 1) s += __shfl_xor_sync(0xffffffffu, s, off);
    if (lane == 0) g_PQ[row] = s;
}

// ============================================================
// K5: main A kernel. Per block: 64 o x 64 i tile for one b.
// A[b,o,i] = P[b,o] + Q[b,i] + ba2 + sum_g c2[g]*|vv[g]+w[g]|
// grid (4,4,8), block 256 (16x16, 4x4 micro-tile), dyn smem 67072 B
// ============================================================
__global__ void __launch_bounds__(256) k_a(const float* __restrict__ ba2p,
                                           float* __restrict__ out)
{
    extern __shared__ float sm[];
    float* sV = sm;                   // [64][129]
    float* sW = sm + 64 * 129;        // [64][129]
    float* sC = sm + 2 * 64 * 129;    // [128]  c2
    float* sP = sC + 128;             // [64]
    float* sQ = sP + 64;              // [64]

    const int b = blockIdx.z, oc = blockIdx.y, ic = blockIdx.x;
    const int tid = threadIdx.x;

    const float4* gv = (const float4*)(g_vv + (b * 256 + oc * 64) * 128);
    const float4* gw = (const float4*)(g_w + (b * 256 + ic * 64) * 128);
    #pragma unroll
    for (int l = tid; l < 2048; l += 256) {
        int r = l >> 5, q = (l & 31) << 2;
        float4 x = gv[l];
        float* d1 = sV + r * 129 + q;
        d1[0] = x.x; d1[1] = x.y; d1[2] = x.z; d1[3] = x.w;
        float4 y = gw[l];
        float* d2 = sW + r * 129 + q;
        d2[0] = y.x; d2[1] = y.y; d2[2] = y.z; d2[3] = y.w;
    }
    if (tid < 128)      sC[tid] = g_c2[tid];
    else if (tid < 192) sP[tid - 128] = g_PQ[b * 256 + oc * 64 + (tid - 128)];
    else                sQ[tid - 192] = g_PQ[2048 + b * 256 + ic * 64 + (tid - 192)];
    __syncthreads();

    const int tx = tid & 15, ty = tid >> 4;
    const float* vp = sV + (ty * 4) * 129;
    const float* wp = sW + (tx * 4) * 129;

    float a00 = 0.f, a01 = 0.f, a02 = 0.f, a03 = 0.f;
    float a10 = 0.f, a11 = 0.f, a12 = 0.f, a13 = 0.f;
    float a20 = 0.f, a21 = 0.f, a22 = 0.f, a23 = 0.f;
    float a30 = 0.f, a31 = 0.f, a32 = 0.f, a33 = 0.f;

    #pragma unroll 4
    for (int g = 0; g < 128; g++) {
        float c2 = sC[g];
        float v0 = vp[g], v1 = vp[g + 129], v2 = vp[g + 258], v3 = vp[g + 387];
        float w0 = wp[g], w1 = wp[g + 129], w2 = wp[g + 258], w3 = wp[g + 387];
        a00 = fmaf(c2, fabsf(v0 + w0), a00);
        a01 = fmaf(c2, fabsf(v0 + w1), a01);
        a02 = fmaf(c2, fabsf(v0 + w2), a02);
        a03 = fmaf(c2, fabsf(v0 + w3), a03);
        a10 = fmaf(c2, fabsf(v1 + w0), a10);
        a11 = fmaf(c2, fabsf(v1 + w1), a11);
        a12 = fmaf(c2, fabsf(v1 + w2), a12);
        a13 = fmaf(c2, fabsf(v1 + w3), a13);
        a20 = fmaf(c2, fabsf(v2 + w0), a20);
        a21 = fmaf(c2, fabsf(v2 + w1), a21);
        a22 = fmaf(c2, fabsf(v2 + w2), a22);
        a23 = fmaf(c2, fabsf(v2 + w3), a23);
        a30 = fmaf(c2, fabsf(v3 + w0), a30);
        a31 = fmaf(c2, fabsf(v3 + w1), a31);
        a32 = fmaf(c2, fabsf(v3 + w2), a32);
        a33 = fmaf(c2, fabsf(v3 + w3), a33);
    }

    const float ba2v = ba2p[0];
    const float q0 = sQ[tx * 4 + 0], q1 = sQ[tx * 4 + 1], q2 = sQ[tx * 4 + 2], q3 = sQ[tx * 4 + 3];
    float accr[4][4] = {{a00,a01,a02,a03},{a10,a11,a12,a13},{a20,a21,a22,a23},{a30,a31,a32,a33}};

    #pragma unroll
    for (int r = 0; r < 4; r++) {
        int og = oc * 64 + ty * 4 + r;
        float pr = sP[ty * 4 + r] + ba2v;
        float4 res;
        res.x = accr[r][0] + pr + q0;
        res.y = accr[r][1] + pr + q1;
        res.z = accr[r][2] + pr + q2;
        res.w = accr[r][3] + pr + q3;
        *(float4*)(out + OFF_A + b * 65536 + og * 256 + ic * 64 + tx * 4) = res;
    }
}

// ============================================================
extern "C" void kernel_launch(void* const* d_in, const int* in_sizes, int n_in,
                              void* d_out, int out_size)
{
    const float* ope   = (const float*)d_in[0];
    const float* ins   = (const float*)d_in[1];
    const float* h_in  = (const float*)d_in[2];
    const float* c_in  = (const float*)d_in[3];
    const float* W_ih  = (const float*)d_in[4];
    const float* W_hh  = (const float*)d_in[5];
    const float* b_ih  = (const float*)d_in[6];
    const float* b_hh  = (const float*)d_in[7];
    const float* Wv0   = (const float*)d_in[8];
    const float* bv0   = (const float*)d_in[9];
    const float* Wv1   = (const float*)d_in[10];
    const float* bv1   = (const float*)d_in[11];
    const float* Wv2   = (const float*)d_in[12];
    const float* bv2   = (const float*)d_in[13];
    const float* Wa0   = (const float*)d_in[14];
    const float* ba0   = (const float*)d_in[15];
    const float* Wa1   = (const float*)d_in[16];
    const float* ba1   = (const float*)d_in[17];
    const float* Wa2   = (const float*)d_in[18];
    const float* ba2   = (const float*)d_in[19];
    float* out = (float*)d_out;

    cudaFuncSetAttribute(k_a, cudaFuncAttributeMaxDynamicSharedMemorySize, 67072);

    k_small<<<8, 256>>>(ope, h_in, c_in, W_ih, W_hh, b_ih, b_hh,
                        Wv0, bv0, Wv1, bv1, Wv2, bv2, Wa0, ba0, Wa1, ba1, out);
    k_m<<<64, 256>>>(Wa0, Wa1, Wa2);
    k_vw<<<256, 128>>>(ope, ins);
    k_pq<<<512, 256>>>();
    k_a<<<dim3(4, 4, 8), 256, 67072>>>(ba2, out);
}

// round 2
// speedup vs baseline: 1.1754x; 1.1754x over previous
#include <cuda_runtime.h>
#include <math.h>

// B=8, D=64, O=256, I=256, G=128
// Output: V(8) | A(8*65536) | hn(8*64) | cn(8*64)
#define OFF_V  0
#define OFF_A  8
#define OFF_HN 524296
#define OFF_CN 524808

// ---- scratch ----
__device__ float g_u[8 * 128];          // per-b const part (incl ba1) after Wa1
__device__ float g_M[2 * 128 * 64];     // [0]=Wa1@Wo, [1]=Wa1@Wi  row-major [g][d]
__device__ float g_c1[128];             // 0.505 * Wa2
__device__ float g_c2d[256];            // 0.495 * Wa2, each value duplicated (pairs)
__device__ float g_vvT[8 * 128 * 256];  // [b][g][o]
__device__ float g_wT[8 * 128 * 256];   // [b][g][i]
__device__ float g_PQ[4096];            // [0:2048) P (b,o), [2048:4096) Q (b,i)

__device__ __forceinline__ float sigm(float x) { return 1.0f / (1.0f + expf(-x)); }

__device__ __forceinline__ unsigned long long addp(unsigned long long a, unsigned long long b) {
    unsigned long long r;
    asm("add.rn.f32x2 %0, %1, %2;" : "=l"(r) : "l"(a), "l"(b));
    return r;
}
__device__ __forceinline__ unsigned long long fmap(unsigned long long a, unsigned long long b, unsigned long long c) {
    unsigned long long r;
    asm("fma.rn.f32x2 %0, %1, %2, %3;" : "=l"(r) : "l"(a), "l"(b), "l"(c));
    return r;
}

// ============================================================
// K1: fused setup. blocks 0..63: M = Wa1@[Wo|Wi] (+c1/c2d).
//     blocks 64..71: per-batch mean/LSTM/V-head/u.
// ============================================================
__global__ void k_setup(const float* __restrict__ ope,
                        const float* __restrict__ h_in,
                        const float* __restrict__ c_in,
                        const float* __restrict__ W_ih,
                        const float* __restrict__ W_hh,
                        const float* __restrict__ b_ih,
                        const float* __restrict__ b_hh,
                        const float* __restrict__ Wv0, const float* __restrict__ bv0,
                        const float* __restrict__ Wv1, const float* __restrict__ bv1,
                        const float* __restrict__ Wv2, const float* __restrict__ bv2,
                        const float* __restrict__ Wa0, const float* __restrict__ ba0,
                        const float* __restrict__ Wa1, const float* __restrict__ ba1,
                        const float* __restrict__ Wa2,
                        float* __restrict__ out)
{
    if (blockIdx.x < 64) {
        // ---- M part ----
        int idx = blockIdx.x * 256 + threadIdx.x;   // 0..16383
        int m = idx >> 13;
        int g = (idx >> 6) & 127;
        int d = idx & 63;
        const float* wa1 = Wa1 + g * 128;
        const float* wa0 = Wa0 + 64 + m * 64 + d;
        float acc = 0.f;
        #pragma unroll 16
        for (int hh = 0; hh < 128; hh++) acc += wa1[hh] * wa0[hh * 192];
        g_M[idx] = acc;
        if (idx < 128) {
            float w2 = Wa2[idx];
            g_c1[idx] = 0.505f * w2;
            g_c2d[2 * idx]     = 0.495f * w2;
            g_c2d[2 * idx + 1] = 0.495f * w2;
        }
        return;
    }

    // ---- small part ----
    __shared__ float sPart[1024];   // [16][64]
    __shared__ float s_state[64], s_h[64], s_gates[256], s_hn[64];
    __shared__ float s_z0[128], s_z1[128], s_t[128];
    const int b = blockIdx.x - 64;
    const int t = threadIdx.x;

    // mean over 256 ope rows: 16 float4 loads per thread
    {
        int dq = t & 15, rc = t >> 4;
        const float* base = ope + (b * 258 + 1 + rc * 16) * 64 + dq * 4;
        float4 s = make_float4(0.f, 0.f, 0.f, 0.f);
        #pragma unroll
        for (int rr = 0; rr < 16; rr++) {
            float4 x = *(const float4*)(base + rr * 64);
            s.x += x.x; s.y += x.y; s.z += x.z; s.w += x.w;
        }
        *(float4*)(sPart + rc * 64 + dq * 4) = s;
    }
    if (t < 64) s_h[t] = h_in[b * 64 + t];
    __syncthreads();
    if (t < 64) {
        float s = 0.f;
        #pragma unroll
        for (int rc = 0; rc < 16; rc++) s += sPart[rc * 64 + t];
        s_state[t] = s * (1.0f / 256.0f);
    }
    __syncthreads();

    {
        float acc = b_ih[t] + b_hh[t];
        const float* wi = W_ih + t * 64;
        const float* wh = W_hh + t * 64;
        #pragma unroll 16
        for (int d = 0; d < 64; d++) acc += wi[d] * s_state[d] + wh[d] * s_h[d];
        s_gates[t] = acc;
    }
    __syncthreads();

    if (t < 64) {
        float ig = sigm(s_gates[t]);
        float fg = sigm(s_gates[64 + t]);
        float gg = tanhf(s_gates[128 + t]);
        float og = sigm(s_gates[192 + t]);
        float cn = fg * c_in[b * 64 + t] + ig * gg;
        float hn = og * tanhf(cn);
        s_hn[t] = hn;
        out[OFF_HN + b * 64 + t] = hn;
        out[OFF_CN + b * 64 + t] = cn;
    }
    __syncthreads();

    if (t < 128) {
        float a = bv0[t];
        const float* w = Wv0 + t * 64;
        #pragma unroll 8
        for (int d = 0; d < 64; d++) a += w[d] * s_hn[d];
        s_z0[t] = a;
    } else {
        int g = t - 128;
        float a = ba0[g];
        const float* w = Wa0 + g * 192;
        #pragma unroll 8
        for (int d = 0; d < 64; d++) a += w[d] * s_hn[d];
        s_t[g] = a;
    }
    __syncthreads();

    if (t < 128) {
        float a = bv1[t];
        const float* w = Wv1 + t * 128;
        #pragma unroll 8
        for (int d = 0; d < 128; d++) a += w[d] * s_z0[d];
        s_z1[t] = (a >= 0.f) ? a : 0.01f * a;
    } else {
        int g = t - 128;
        float a = ba1[g];
        const float* w = Wa1 + g * 128;
        #pragma unroll 8
        for (int d = 0; d < 128; d++) a += w[d] * s_t[d];
        g_u[b * 128 + g] = a;
    }
    __syncthreads();

    if (t == 0) {
        float a = bv2[0];
        #pragma unroll 8
        for (int k = 0; k < 128; k++) a += Wv2[k] * s_z1[k];
        out[OFF_V + b] = a;
    }
}

// ============================================================
// K2: vv/w rows (transposed output layout [b][g][x]) + fused P/Q.
// grid 256, block 128 (thread = g), 16 rows per block.
// ============================================================
__global__ void __launch_bounds__(128) k_vw(const float* __restrict__ ope,
                                            const float* __restrict__ ins)
{
    __shared__ float sIn[1024];     // 16 rows x 64
    __shared__ float sRed[2048];    // [16][128]
    const int rbase = blockIdx.x * 16;
    const int g = threadIdx.x;
    const bool isV = (rbase < 2048);
    const int rb = isV ? rbase : (rbase - 2048);
    const int b = rb >> 8;
    const int x0 = rb & 255;

    const float4* Mrow = (const float4*)(g_M + (isV ? 0 : 8192) + g * 64);
    float4 m[16];
    #pragma unroll
    for (int j = 0; j < 16; j++) m[j] = Mrow[j];

    // 16 consecutive rows are contiguous in both sources
    const float4* s4 = (const float4*)(isV ? (ope + (b * 258 + 1 + x0) * 64)
                                           : (ins + (b * 256 + x0) * 64));
    ((float4*)sIn)[g] = s4[g];
    ((float4*)sIn)[g + 128] = s4[g + 128];

    const float u = isV ? g_u[b * 128 + g] : 0.0f;
    const float c1 = g_c1[g];
    __syncthreads();

    float accs[16];
    #pragma unroll
    for (int r = 0; r < 16; r++) {
        float a = u;
        const float4* ip = (const float4*)(sIn + r * 64);
        #pragma unroll
        for (int j = 0; j < 16; j++) {
            float4 x = ip[j];
            a += m[j].x * x.x + m[j].y * x.y + m[j].z * x.z + m[j].w * x.w;
        }
        accs[r] = a;
        sRed[r * 128 + g] = c1 * a;
    }

    // transposed global write: 16 consecutive x for fixed g
    float* dst = (isV ? g_vvT : g_wT) + b * 32768 + g * 256 + x0;
    #pragma unroll
    for (int r4 = 0; r4 < 4; r4++)
        *(float4*)(dst + r4 * 4) = make_float4(accs[r4*4], accs[r4*4+1], accs[r4*4+2], accs[r4*4+3]);

    __syncthreads();
    // P/Q reduction: warp w reduces rows 4w..4w+3
    int w = g >> 5, lane = g & 31;
    #pragma unroll
    for (int rr = 0; rr < 4; rr++) {
        int row = w * 4 + rr;
        float4 xx = ((const float4*)(sRed + row * 128))[lane];
        float s = xx.x + xx.y + xx.z + xx.w;
        #pragma unroll
        for (int off = 16; off; off >>= 1) s += __shfl_xor_sync(0xffffffffu, s, off);
        if (lane == 0) g_PQ[rbase + row] = s;
    }
}

// ============================================================
// K3: A tile kernel, packed f32x2.
// A[b,o,i] = P[o]+Q[i]+ba2 + sum_g c2[g]*|vv[g,o]+w[g,i]|
// grid (4,4,8), block 256 (16x16 threads, 4o x 4i micro-tile)
// smem: sVd[g][2o] (v duplicated), sW[g][i], c2 dup, P, Q
// ============================================================
__global__ void __launch_bounds__(256) k_a(const float* __restrict__ ba2p,
                                           float* __restrict__ out)
{
    extern __shared__ float sm[];
    float* sVd = sm;            // 128*128
    float* sW  = sm + 16384;    // 128*64
    float* sC2 = sm + 24576;    // 256 (duplicated pairs)
    float* sP  = sm + 24832;    // 64
    float* sQ  = sm + 24896;    // 64
    const int b = blockIdx.z, oc = blockIdx.y, ic = blockIdx.x;
    const int tid = threadIdx.x;

    const float* vsrc = g_vvT + b * 32768 + oc * 64;
    const float* wsrc = g_wT  + b * 32768 + ic * 64;
    #pragma unroll
    for (int l = tid; l < 2048; l += 256) {
        int gg = l >> 4, q = (l & 15) << 2;
        float4 wv = *(const float4*)(wsrc + gg * 256 + q);
        *(float4*)(sW + gg * 64 + q) = wv;
        float4 vv = *(const float4*)(vsrc + gg * 256 + q);
        float* vd = sVd + gg * 128 + q * 2;
        ((float4*)vd)[0] = make_float4(vv.x, vv.x, vv.y, vv.y);
        ((float4*)vd)[1] = make_float4(vv.z, vv.z, vv.w, vv.w);
    }
    sC2[tid] = g_c2d[tid & 255];
    if (tid < 64)       sP[tid] = g_PQ[b * 256 + oc * 64 + tid];
    else if (tid < 128) sQ[tid - 64] = g_PQ[2048 + b * 256 + ic * 64 + (tid - 64)];
    __syncthreads();

    const int tx = tid & 15, ty = tid >> 4;
    unsigned long long a00 = 0, a01 = 0, a10 = 0, a11 = 0,
                       a20 = 0, a21 = 0, a30 = 0, a31 = 0;
    const float* vbase = sVd + ty * 8;
    const float* wbase = sW + tx * 4;
    const unsigned long long* c2base = (const unsigned long long*)sC2;
    const unsigned long long MASK = 0x7FFFFFFF7FFFFFFFULL;

    #pragma unroll 4
    for (int gg = 0; gg < 128; gg++) {
        ulonglong2 vp01 = *(const ulonglong2*)(vbase + gg * 128);
        ulonglong2 vp23 = *(const ulonglong2*)(vbase + gg * 128 + 4);
        ulonglong2 wp   = *(const ulonglong2*)(wbase + gg * 64);
        unsigned long long c2 = c2base[gg];
        unsigned long long t;
        t = addp(vp01.x, wp.x) & MASK;  a00 = fmap(c2, t, a00);
        t = addp(vp01.x, wp.y) & MASK;  a01 = fmap(c2, t, a01);
        t = addp(vp01.y, wp.x) & MASK;  a10 = fmap(c2, t, a10);
        t = addp(vp01.y, wp.y) & MASK;  a11 = fmap(c2, t, a11);
        t = addp(vp23.x, wp.x) & MASK;  a20 = fmap(c2, t, a20);
        t = addp(vp23.x, wp.y) & MASK;  a21 = fmap(c2, t, a21);
        t = addp(vp23.y, wp.x) & MASK;  a30 = fmap(c2, t, a30);
        t = addp(vp23.y, wp.y) & MASK;  a31 = fmap(c2, t, a31);
    }

    const float ba2v = ba2p[0];
    float4 q4 = *(const float4*)(sQ + tx * 4);
    unsigned long long acc[4][2] = {{a00,a01},{a10,a11},{a20,a21},{a30,a31}};
    #pragma unroll
    for (int r = 0; r < 4; r++) {
        float pr = sP[ty * 4 + r] + ba2v;
        float4 res;
        res.x = __uint_as_float((unsigned)(acc[r][0] & 0xffffffffULL)) + pr + q4.x;
        res.y = __uint_as_float((unsigned)(acc[r][0] >> 32))           + pr + q4.y;
        res.z = __uint_as_float((unsigned)(acc[r][1] & 0xffffffffULL)) + pr + q4.z;
        res.w = __uint_as_float((unsigned)(acc[r][1] >> 32))           + pr + q4.w;
        int og = oc * 64 + ty * 4 + r;
        *(float4*)(out + OFF_A + b * 65536 + og * 256 + ic * 64 + tx * 4) = res;
    }
}

// ============================================================
extern "C" void kernel_launch(void* const* d_in, const int* in_sizes, int n_in,
                              void* d_out, int out_size)
{
    const float* ope   = (const float*)d_in[0];
    const float* ins   = (const float*)d_in[1];
    const float* h_in  = (const float*)d_in[2];
    const float* c_in  = (const float*)d_in[3];
    const float* W_ih  = (const float*)d_in[4];
    const float* W_hh  = (const float*)d_in[5];
    const float* b_ih  = (const float*)d_in[6];
    const float* b_hh  = (const float*)d_in[7];
    const float* Wv0   = (const float*)d_in[8];
    const float* bv0   = (const float*)d_in[9];
    const float* Wv1   = (const float*)d_in[10];
    const float* bv1   = (const float*)d_in[11];
    const float* Wv2   = (const float*)d_in[12];
    const float* bv2   = (const float*)d_in[13];
    const float* Wa0   = (const float*)d_in[14];
    const float* ba0   = (const float*)d_in[15];
    const float* Wa1   = (const float*)d_in[16];
    const float* ba1   = (const float*)d_in[17];
    const float* Wa2   = (const float*)d_in[18];
    const float* ba2   = (const float*)d_in[19];
    float* out = (float*)d_out;

    cudaFuncSetAttribute(k_a, cudaFuncAttributeMaxDynamicSharedMemorySize, 99840);

    k_setup<<<72, 256>>>(ope, h_in, c_in, W_ih, W_hh, b_ih, b_hh,
                         Wv0, bv0, Wv1, bv1, Wv2, bv2, Wa0, ba0, Wa1, ba1, Wa2, out);
    k_vw<<<256, 128>>>(ope, ins);
    k_a<<<dim3(4, 4, 8), 256, 99840>>>(ba2, out);
}

// round 3
// speedup vs baseline: 1.8421x; 1.5673x over previous
#include <cuda_runtime.h>
#include <math.h>

// B=8, D=64, O=256, I=256, G=128
// Output: V(8) | A(8*65536) | hn(8*64) | cn(8*64)
#define OFF_V  0
#define OFF_A  8
#define OFF_HN 524296
#define OFF_CN 524808

// ---- scratch ----
__device__ float g_u[8 * 128];
__device__ float g_M[2 * 128 * 64];
__device__ float g_c1[128];
__device__ float g_c2d[256];
__device__ float g_vvT[8 * 128 * 256];  // [b][g][o]
__device__ float g_wT[8 * 128 * 256];   // [b][g][i]
__device__ float g_PQ[4096];

__device__ __forceinline__ float sigm(float x) { return 1.0f / (1.0f + expf(-x)); }

__device__ __forceinline__ float warp_sum(float v) {
    #pragma unroll
    for (int o = 16; o; o >>= 1) v += __shfl_xor_sync(0xffffffffu, v, o);
    return v;
}

__device__ __forceinline__ unsigned long long addp(unsigned long long a, unsigned long long b) {
    unsigned long long r;
    asm("add.rn.f32x2 %0, %1, %2;" : "=l"(r) : "l"(a), "l"(b));
    return r;
}
__device__ __forceinline__ unsigned long long fmap(unsigned long long a, unsigned long long b, unsigned long long c) {
    unsigned long long r;
    asm("fma.rn.f32x2 %0, %1, %2, %3;" : "=l"(r) : "l"(a), "l"(b), "l"(c));
    return r;
}

// ============================================================
// K1: fused setup.
//   blocks 0..63 : M = Wa1@[Wo|Wi]  (+ c1 / c2d)
//   blocks 64..71: per-batch mean / LSTM / V-head / u  (warp-coalesced)
// ============================================================
__global__ void __launch_bounds__(256) k_setup(
                        const float* __restrict__ ope,
                        const float* __restrict__ h_in,
                        const float* __restrict__ c_in,
                        const float* __restrict__ W_ih,
                        const float* __restrict__ W_hh,
                        const float* __restrict__ b_ih,
                        const float* __restrict__ b_hh,
                        const float* __restrict__ Wv0, const float* __restrict__ bv0,
                        const float* __restrict__ Wv1, const float* __restrict__ bv1,
                        const float* __restrict__ Wv2, const float* __restrict__ bv2,
                        const float* __restrict__ Wa0, const float* __restrict__ ba0,
                        const float* __restrict__ Wa1, const float* __restrict__ ba1,
                        const float* __restrict__ Wa2,
                        float* __restrict__ out)
{
    if (blockIdx.x < 64) {
        int idx = blockIdx.x * 256 + threadIdx.x;   // 0..16383
        int m = idx >> 13;
        int g = (idx >> 6) & 127;
        int d = idx & 63;
        const float* wa1 = Wa1 + g * 128;
        const float* wa0 = Wa0 + 64 + m * 64 + d;
        float acc = 0.f;
        #pragma unroll 16
        for (int hh = 0; hh < 128; hh++) acc += wa1[hh] * wa0[hh * 192];
        g_M[idx] = acc;
        if (idx < 128) {
            float w2 = Wa2[idx];
            g_c1[idx] = 0.505f * w2;
            g_c2d[2 * idx]     = 0.495f * w2;
            g_c2d[2 * idx + 1] = 0.495f * w2;
        }
        return;
    }

    // ---- small part: warp-per-row dense layers ----
    __shared__ float sPart[1024];
    __shared__ float s_state[64], s_h[64], s_gates[256], s_hn[64];
    __shared__ float s_z0[128], s_z1[128], s_t[128];
    const int b = blockIdx.x - 64;
    const int t = threadIdx.x;
    const int w = t >> 5, lane = t & 31;

    // mean over 256 ope rows: coalesced float4 loads
    {
        int dq = t & 15, rc = t >> 4;
        const float* base = ope + (b * 258 + 1 + rc * 16) * 64 + dq * 4;
        float4 s = make_float4(0.f, 0.f, 0.f, 0.f);
        #pragma unroll
        for (int rr = 0; rr < 16; rr++) {
            float4 x = *(const float4*)(base + rr * 64);
            s.x += x.x; s.y += x.y; s.z += x.z; s.w += x.w;
        }
        *(float4*)(sPart + rc * 64 + dq * 4) = s;
    }
    if (t < 64) s_h[t] = h_in[b * 64 + t];
    __syncthreads();
    if (t < 64) {
        float s = 0.f;
        #pragma unroll
        for (int rc = 0; rc < 16; rc++) s += sPart[rc * 64 + t];
        s_state[t] = s * (1.0f / 256.0f);
    }
    __syncthreads();

    // gates: 256 rows, K=64. warp w -> rows w*32..w*32+31, lanes over K.
    {
        float st0 = s_state[lane], st1 = s_state[lane + 32];
        float hh0 = s_h[lane],     hh1 = s_h[lane + 32];
        #pragma unroll 4
        for (int j = 0; j < 32; j++) {
            int r = w * 32 + j;
            const float* wi = W_ih + r * 64;
            const float* wh = W_hh + r * 64;
            float acc = wi[lane] * st0 + wi[lane + 32] * st1
                      + wh[lane] * hh0 + wh[lane + 32] * hh1;
            acc = warp_sum(acc);
            if (lane == 0) s_gates[r] = acc + b_ih[r] + b_hh[r];
        }
    }
    __syncthreads();

    if (t < 64) {
        float ig = sigm(s_gates[t]);
        float fg = sigm(s_gates[64 + t]);
        float gg = tanhf(s_gates[128 + t]);
        float og = sigm(s_gates[192 + t]);
        float cn = fg * c_in[b * 64 + t] + ig * gg;
        float hn = og * tanhf(cn);
        s_hn[t] = hn;
        out[OFF_HN + b * 64 + t] = hn;
        out[OFF_CN + b * 64 + t] = cn;
    }
    __syncthreads();

    // z0 (Wv0: 128 rows, K=64) on warps 0..3 ; t-vec (Wa0[:, :64]: 128 rows, stride 192) on warps 4..7
    {
        float x0 = s_hn[lane], x1 = s_hn[lane + 32];
        if (w < 4) {
            #pragma unroll 4
            for (int j = 0; j < 32; j++) {
                int r = w * 32 + j;
                const float* wr = Wv0 + r * 64;
                float acc = wr[lane] * x0 + wr[lane + 32] * x1;
                acc = warp_sum(acc);
                if (lane == 0) s_z0[r] = acc + bv0[r];
            }
        } else {
            #pragma unroll 4
            for (int j = 0; j < 32; j++) {
                int r = (w - 4) * 32 + j;
                const float* wr = Wa0 + r * 192;
                float acc = wr[lane] * x0 + wr[lane + 32] * x1;
                acc = warp_sum(acc);
                if (lane == 0) s_t[r] = acc + ba0[r];
            }
        }
    }
    __syncthreads();

    // z1 (Wv1: 128 rows, K=128) warps 0..3 ; u (Wa1: 128 rows, K=128) warps 4..7
    {
        if (w < 4) {
            float4 x = *(const float4*)(s_z0 + lane * 4);
            #pragma unroll 4
            for (int j = 0; j < 32; j++) {
                int r = w * 32 + j;
                float4 ww = *(const float4*)(Wv1 + r * 128 + lane * 4);
                float acc = ww.x * x.x + ww.y * x.y + ww.z * x.z + ww.w * x.w;
                acc = warp_sum(acc);
                if (lane == 0) {
                    acc += bv1[r];
                    s_z1[r] = (acc >= 0.f) ? acc : 0.01f * acc;
                }
            }
        } else {
            float4 x = *(const float4*)(s_t + lane * 4);
            #pragma unroll 4
            for (int j = 0; j < 32; j++) {
                int r = (w - 4) * 32 + j;
                float4 ww = *(const float4*)(Wa1 + r * 128 + lane * 4);
                float acc = ww.x * x.x + ww.y * x.y + ww.z * x.z + ww.w * x.w;
                acc = warp_sum(acc);
                if (lane == 0) g_u[b * 128 + r] = acc + ba1[r];
            }
        }
    }
    __syncthreads();

    if (w == 0) {
        float4 x = *(const float4*)(s_z1 + lane * 4);
        float4 ww = *(const float4*)(Wv2 + lane * 4);
        float acc = ww.x * x.x + ww.y * x.y + ww.z * x.z + ww.w * x.w;
        acc = warp_sum(acc);
        if (lane == 0) out[OFF_V + b] = acc + bv2[0];
    }
}

// ============================================================
// K2: vv/w rows (transposed output [b][g][x]) + fused P/Q.
// grid 256, block 128 (thread = g), 16 rows per block.
// ============================================================
__global__ void __launch_bounds__(128) k_vw(const float* __restrict__ ope,
                                            const float* __restrict__ ins)
{
    __shared__ float sIn[1024];
    __shared__ float sRed[2048];
    const int rbase = blockIdx.x * 16;
    const int g = threadIdx.x;
    const bool isV = (rbase < 2048);
    const int rb = isV ? rbase : (rbase - 2048);
    const int b = rb >> 8;
    const int x0 = rb & 255;

    const float4* Mrow = (const float4*)(g_M + (isV ? 0 : 8192) + g * 64);
    float4 m[16];
    #pragma unroll
    for (int j = 0; j < 16; j++) m[j] = Mrow[j];

    const float4* s4 = (const float4*)(isV ? (ope + (b * 258 + 1 + x0) * 64)
                                           : (ins + (b * 256 + x0) * 64));
    ((float4*)sIn)[g] = s4[g];
    ((float4*)sIn)[g + 128] = s4[g + 128];

    const float u = isV ? g_u[b * 128 + g] : 0.0f;
    const float c1 = g_c1[g];
    __syncthreads();

    float accs[16];
    #pragma unroll
    for (int r = 0; r < 16; r++) {
        float a = u;
        const float4* ip = (const float4*)(sIn + r * 64);
        #pragma unroll
        for (int j = 0; j < 16; j++) {
            float4 x = ip[j];
            a += m[j].x * x.x + m[j].y * x.y + m[j].z * x.z + m[j].w * x.w;
        }
        accs[r] = a;
        sRed[r * 128 + g] = c1 * a;
    }

    float* dst = (isV ? g_vvT : g_wT) + b * 32768 + g * 256 + x0;
    #pragma unroll
    for (int r4 = 0; r4 < 4; r4++)
        *(float4*)(dst + r4 * 4) = make_float4(accs[r4*4], accs[r4*4+1], accs[r4*4+2], accs[r4*4+3]);

    __syncthreads();
    int ww = g >> 5, lane = g & 31;
    #pragma unroll
    for (int rr = 0; rr < 4; rr++) {
        int row = ww * 4 + rr;
        float4 xx = ((const float4*)(sRed + row * 128))[lane];
        float s = xx.x + xx.y + xx.z + xx.w;
        #pragma unroll
        for (int off = 16; off; off >>= 1) s += __shfl_xor_sync(0xffffffffu, s, off);
        if (lane == 0) g_PQ[rbase + row] = s;
    }
}

// ============================================================
// K3: A tile kernel, packed f32x2.
// ============================================================
__global__ void __launch_bounds__(256) k_a(const float* __restrict__ ba2p,
                                           float* __restrict__ out)
{
    extern __shared__ float sm[];
    float* sVd = sm;            // 128*128
    float* sW  = sm + 16384;    // 128*64
    float* sC2 = sm + 24576;    // 256
    float* sP  = sm + 24832;    // 64
    float* sQ  = sm + 24896;    // 64
    const int b = blockIdx.z, oc = blockIdx.y, ic = blockIdx.x;
    const int tid = threadIdx.x;

    const float* vsrc = g_vvT + b * 32768 + oc * 64;
    const float* wsrc = g_wT  + b * 32768 + ic * 64;
    #pragma unroll
    for (int l = tid; l < 2048; l += 256) {
        int gg = l >> 4, q = (l & 15) << 2;
        float4 wv = *(const float4*)(wsrc + gg * 256 + q);
        *(float4*)(sW + gg * 64 + q) = wv;
        float4 vv = *(const float4*)(vsrc + gg * 256 + q);
        float* vd = sVd + gg * 128 + q * 2;
        ((float4*)vd)[0] = make_float4(vv.x, vv.x, vv.y, vv.y);
        ((float4*)vd)[1] = make_float4(vv.z, vv.z, vv.w, vv.w);
    }
    sC2[tid] = g_c2d[tid & 255];
    if (tid < 64)       sP[tid] = g_PQ[b * 256 + oc * 64 + tid];
    else if (tid < 128) sQ[tid - 64] = g_PQ[2048 + b * 256 + ic * 64 + (tid - 64)];
    __syncthreads();

    const int tx = tid & 15, ty = tid >> 4;
    unsigned long long a00 = 0, a01 = 0, a10 = 0, a11 = 0,
                       a20 = 0, a21 = 0, a30 = 0, a31 = 0;
    const float* vbase = sVd + ty * 8;
    const float* wbase = sW + tx * 4;
    const unsigned long long* c2base = (const unsigned long long*)sC2;
    const unsigned long long MASK = 0x7FFFFFFF7FFFFFFFULL;

    #pragma unroll 4
    for (int gg = 0; gg < 128; gg++) {
        ulonglong2 vp01 = *(const ulonglong2*)(vbase + gg * 128);
        ulonglong2 vp23 = *(const ulonglong2*)(vbase + gg * 128 + 4);
        ulonglong2 wp   = *(const ulonglong2*)(wbase + gg * 64);
        unsigned long long c2 = c2base[gg];
        unsigned long long t;
        t = addp(vp01.x, wp.x) & MASK;  a00 = fmap(c2, t, a00);
        t = addp(vp01.x, wp.y) & MASK;  a01 = fmap(c2, t, a01);
        t = addp(vp01.y, wp.x) & MASK;  a10 = fmap(c2, t, a10);
        t = addp(vp01.y, wp.y) & MASK;  a11 = fmap(c2, t, a11);
        t = addp(vp23.x, wp.x) & MASK;  a20 = fmap(c2, t, a20);
        t = addp(vp23.x, wp.y) & MASK;  a21 = fmap(c2, t, a21);
        t = addp(vp23.y, wp.x) & MASK;  a30 = fmap(c2, t, a30);
        t = addp(vp23.y, wp.y) & MASK;  a31 = fmap(c2, t, a31);
    }

    const float ba2v = ba2p[0];
    float4 q4 = *(const float4*)(sQ + tx * 4);
    unsigned long long acc[4][2] = {{a00,a01},{a10,a11},{a20,a21},{a30,a31}};
    #pragma unroll
    for (int r = 0; r < 4; r++) {
        float pr = sP[ty * 4 + r] + ba2v;
        float4 res;
        res.x = __uint_as_float((unsigned)(acc[r][0] & 0xffffffffULL)) + pr + q4.x;
        res.y = __uint_as_float((unsigned)(acc[r][0] >> 32))           + pr + q4.y;
        res.z = __uint_as_float((unsigned)(acc[r][1] & 0xffffffffULL)) + pr + q4.z;
        res.w = __uint_as_float((unsigned)(acc[r][1] >> 32))           + pr + q4.w;
        int og = oc * 64 + ty * 4 + r;
        *(float4*)(out + OFF_A + b * 65536 + og * 256 + ic * 64 + tx * 4) = res;
    }
}

// ============================================================
extern "C" void kernel_launch(void* const* d_in, const int* in_sizes, int n_in,
                              void* d_out, int out_size)
{
    const float* ope   = (const float*)d_in[0];
    const float* ins   = (const float*)d_in[1];
    const float* h_in  = (const float*)d_in[2];
    const float* c_in  = (const float*)d_in[3];
    const float* W_ih  = (const float*)d_in[4];
    const float* W_hh  = (const float*)d_in[5];
    const float* b_ih  = (const float*)d_in[6];
    const float* b_hh  = (const float*)d_in[7];
    const float* Wv0   = (const float*)d_in[8];
    const float* bv0   = (const float*)d_in[9];
    const float* Wv1   = (const float*)d_in[10];
    const float* bv1   = (const float*)d_in[11];
    const float* Wv2   = (const float*)d_in[12];
    const float* bv2   = (const float*)d_in[13];
    const float* Wa0   = (const float*)d_in[14];
    const float* ba0   = (const float*)d_in[15];
    const float* Wa1   = (const float*)d_in[16];
    const float* ba1   = (const float*)d_in[17];
    const float* Wa2   = (const float*)d_in[18];
    const float* ba2   = (const float*)d_in[19];
    float* out = (float*)d_out;

    cudaFuncSetAttribute(k_a, cudaFuncAttributeMaxDynamicSharedMemorySize, 99840);

    k_setup<<<72, 256>>>(ope, h_in, c_in, W_ih, W_hh, b_ih, b_hh,
                         Wv0, bv0, Wv1, bv1, Wv2, bv2, Wa0, ba0, Wa1, ba1, Wa2, out);
    k_vw<<<256, 128>>>(ope, ins);
    k_a<<<dim3(4, 4, 8), 256, 99840>>>(ba2, out);
}

// round 4
// speedup vs baseline: 2.1447x; 1.1643x over previous
#include <cuda_runtime.h>
#include <math.h>

// B=8, D=64, O=256, I=256, G=128
// Output: V(8) | A(8*65536) | hn(8*64) | cn(8*64)
#define OFF_V  0
#define OFF_A  8
#define OFF_HN 524296
#define OFF_CN 524808

// ---- scratch ----
__device__ float g_u[8 * 128];
__device__ float g_M[2 * 128 * 64];
__device__ float g_c1[128];
__device__ float g_c2d[256];
__device__ float g_vvT[8 * 128 * 256];  // [b][g][o]
__device__ float g_wT[8 * 128 * 256];   // [b][g][i]
__device__ float g_PQ[4096];

__device__ __forceinline__ float sigm(float x) { return 1.0f / (1.0f + expf(-x)); }

__device__ __forceinline__ float warp_sum(float v) {
    #pragma unroll
    for (int o = 16; o; o >>= 1) v += __shfl_xor_sync(0xffffffffu, v, o);
    return v;
}

__device__ __forceinline__ unsigned long long addp(unsigned long long a, unsigned long long b) {
    unsigned long long r;
    asm("add.rn.f32x2 %0, %1, %2;" : "=l"(r) : "l"(a), "l"(b));
    return r;
}
__device__ __forceinline__ unsigned long long fmap(unsigned long long a, unsigned long long b, unsigned long long c) {
    unsigned long long r;
    asm("fma.rn.f32x2 %0, %1, %2, %3;" : "=l"(r) : "l"(a), "l"(b), "l"(c));
    return r;
}

// ============================================================
// K1: fused setup.
//   blocks 0..15 : M = Wa1@[Wo|Wi]  (smem-staged mini-GEMM)
//   block  16    : c1 / c2d
//   blocks 17..24: per-batch mean / LSTM / V-head / u
// ============================================================
__global__ void __launch_bounds__(256) k_setup(
                        const float* __restrict__ ope,
                        const float* __restrict__ h_in,
                        const float* __restrict__ c_in,
                        const float* __restrict__ W_ih,
                        const float* __restrict__ W_hh,
                        const float* __restrict__ b_ih,
                        const float* __restrict__ b_hh,
                        const float* __restrict__ Wv0, const float* __restrict__ bv0,
                        const float* __restrict__ Wv1, const float* __restrict__ bv1,
                        const float* __restrict__ Wv2, const float* __restrict__ bv2,
                        const float* __restrict__ Wa0, const float* __restrict__ ba0,
                        const float* __restrict__ Wa1, const float* __restrict__ ba1,
                        const float* __restrict__ Wa2,
                        float* __restrict__ out)
{
    const int t = threadIdx.x;

    if (blockIdx.x < 16) {
        // ---- M-part: block -> (m, 16-row g chunk) ----
        __shared__ __align__(16) float sA[16 * 129];   // Wa1 rows, padded
        __shared__ __align__(16) float sB[128 * 72];   // Wa0 col slice [hh][d], padded
        const int m  = blockIdx.x >> 3;
        const int gc = blockIdx.x & 7;

        // stage A: 2048 contiguous floats, coalesced
        #pragma unroll
        for (int i = 0; i < 8; i++) {
            int idx = t + i * 256;
            sA[(idx >> 7) * 129 + (idx & 127)] = Wa1[gc * 2048 + idx];
        }
        // stage B: rows hh of Wa0[:, 64+m*64 .. +63], float4 coalesced per row
        {
            int hh0 = t >> 4, c4 = t & 15;
            #pragma unroll
            for (int i = 0; i < 8; i++) {
                int hh = hh0 + i * 16;
                float4 v = *(const float4*)(Wa0 + hh * 192 + 64 + m * 64 + c4 * 4);
                *(float4*)(sB + hh * 72 + c4 * 4) = v;
            }
        }
        __syncthreads();

        const int g = t >> 4, dg = t & 15;
        float4 acc = make_float4(0.f, 0.f, 0.f, 0.f);
        const float* arow = sA + g * 129;
        const float* bcol = sB + dg * 4;
        #pragma unroll 8
        for (int hh = 0; hh < 128; hh++) {
            float a = arow[hh];
            float4 bv = *(const float4*)(bcol + hh * 72);
            acc.x += a * bv.x; acc.y += a * bv.y; acc.z += a * bv.z; acc.w += a * bv.w;
        }
        *(float4*)(g_M + m * 8192 + (gc * 16 + g) * 64 + dg * 4) = acc;
        return;
    }

    if (blockIdx.x == 16) {
        if (t < 128) {
            float w2 = Wa2[t];
            g_c1[t] = 0.505f * w2;
            g_c2d[2 * t]     = 0.495f * w2;
            g_c2d[2 * t + 1] = 0.495f * w2;
        }
        return;
    }

    // ---- small part: warp-per-row dense layers (per batch) ----
    __shared__ float sPart[1024];
    __shared__ float s_state[64], s_h[64], s_gates[256], s_hn[64];
    __shared__ float s_z0[128], s_z1[128], s_t[128];
    const int b = blockIdx.x - 17;
    const int w = t >> 5, lane = t & 31;

    // mean over 256 ope rows: coalesced float4 loads
    {
        int dq = t & 15, rc = t >> 4;
        const float* base = ope + (b * 258 + 1 + rc * 16) * 64 + dq * 4;
        float4 s = make_float4(0.f, 0.f, 0.f, 0.f);
        #pragma unroll
        for (int rr = 0; rr < 16; rr++) {
            float4 x = *(const float4*)(base + rr * 64);
            s.x += x.x; s.y += x.y; s.z += x.z; s.w += x.w;
        }
        *(float4*)(sPart + rc * 64 + dq * 4) = s;
    }
    if (t < 64) s_h[t] = h_in[b * 64 + t];
    __syncthreads();
    if (t < 64) {
        float s = 0.f;
        #pragma unroll
        for (int rc = 0; rc < 16; rc++) s += sPart[rc * 64 + t];
        s_state[t] = s * (1.0f / 256.0f);
    }
    __syncthreads();

    // gates: 256 rows, K=64. warp w -> rows w*32..w*32+31, lanes over K.
    {
        float st0 = s_state[lane], st1 = s_state[lane + 32];
        float hh0 = s_h[lane],     hh1 = s_h[lane + 32];
        #pragma unroll 4
        for (int j = 0; j < 32; j++) {
            int r = w * 32 + j;
            const float* wi = W_ih + r * 64;
            const float* wh = W_hh + r * 64;
            float acc = wi[lane] * st0 + wi[lane + 32] * st1
                      + wh[lane] * hh0 + wh[lane + 32] * hh1;
            acc = warp_sum(acc);
            if (lane == 0) s_gates[r] = acc + b_ih[r] + b_hh[r];
        }
    }
    __syncthreads();

    if (t < 64) {
        float ig = sigm(s_gates[t]);
        float fg = sigm(s_gates[64 + t]);
        float gg = tanhf(s_gates[128 + t]);
        float og = sigm(s_gates[192 + t]);
        float cn = fg * c_in[b * 64 + t] + ig * gg;
        float hn = og * tanhf(cn);
        s_hn[t] = hn;
        out[OFF_HN + b * 64 + t] = hn;
        out[OFF_CN + b * 64 + t] = cn;
    }
    __syncthreads();

    // z0 (Wv0, K=64) warps 0..3 ; t-vec (Wa0[:, :64], stride 192) warps 4..7
    {
        float x0 = s_hn[lane], x1 = s_hn[lane + 32];
        if (w < 4) {
            #pragma unroll 4
            for (int j = 0; j < 32; j++) {
                int r = w * 32 + j;
                const float* wr = Wv0 + r * 64;
                float acc = wr[lane] * x0 + wr[lane + 32] * x1;
                acc = warp_sum(acc);
                if (lane == 0) s_z0[r] = acc + bv0[r];
            }
        } else {
            #pragma unroll 4
            for (int j = 0; j < 32; j++) {
                int r = (w - 4) * 32 + j;
                const float* wr = Wa0 + r * 192;
                float acc = wr[lane] * x0 + wr[lane + 32] * x1;
                acc = warp_sum(acc);
                if (lane == 0) s_t[r] = acc + ba0[r];
            }
        }
    }
    __syncthreads();

    // z1 (Wv1, K=128) warps 0..3 ; u (Wa1, K=128) warps 4..7
    {
        if (w < 4) {
            float4 x = *(const float4*)(s_z0 + lane * 4);
            #pragma unroll 4
            for (int j = 0; j < 32; j++) {
                int r = w * 32 + j;
                float4 ww = *(const float4*)(Wv1 + r * 128 + lane * 4);
                float acc = ww.x * x.x + ww.y * x.y + ww.z * x.z + ww.w * x.w;
                acc = warp_sum(acc);
                if (lane == 0) {
                    acc += bv1[r];
                    s_z1[r] = (acc >= 0.f) ? acc : 0.01f * acc;
                }
            }
        } else {
            float4 x = *(const float4*)(s_t + lane * 4);
            #pragma unroll 4
            for (int j = 0; j < 32; j++) {
                int r = (w - 4) * 32 + j;
                float4 ww = *(const float4*)(Wa1 + r * 128 + lane * 4);
                float acc = ww.x * x.x + ww.y * x.y + ww.z * x.z + ww.w * x.w;
                acc = warp_sum(acc);
                if (lane == 0) g_u[b * 128 + r] = acc + ba1[r];
            }
        }
    }
    __syncthreads();

    if (w == 0) {
        float4 x = *(const float4*)(s_z1 + lane * 4);
        float4 ww = *(const float4*)(Wv2 + lane * 4);
        float acc = ww.x * x.x + ww.y * x.y + ww.z * x.z + ww.w * x.w;
        acc = warp_sum(acc);
        if (lane == 0) out[OFF_V + b] = acc + bv2[0];
    }
}

// ============================================================
// K2: vv/w rows (transposed output [b][g][x]) + fused P/Q.
// grid 256, block 128 (thread = g), 16 rows per block.
// ============================================================
__global__ void __launch_bounds__(128) k_vw(const float* __restrict__ ope,
                                            const float* __restrict__ ins)
{
    __shared__ float sIn[1024];
    __shared__ float sRed[2048];
    const int rbase = blockIdx.x * 16;
    const int g = threadIdx.x;
    const bool isV = (rbase < 2048);
    const int rb = isV ? rbase : (rbase - 2048);
    const int b = rb >> 8;
    const int x0 = rb & 255;

    const float4* Mrow = (const float4*)(g_M + (isV ? 0 : 8192) + g * 64);
    float4 m[16];
    #pragma unroll
    for (int j = 0; j < 16; j++) m[j] = Mrow[j];

    const float4* s4 = (const float4*)(isV ? (ope + (b * 258 + 1 + x0) * 64)
                                           : (ins + (b * 256 + x0) * 64));
    ((float4*)sIn)[g] = s4[g];
    ((float4*)sIn)[g + 128] = s4[g + 128];

    const float u = isV ? g_u[b * 128 + g] : 0.0f;
    const float c1 = g_c1[g];
    __syncthreads();

    float accs[16];
    #pragma unroll
    for (int r = 0; r < 16; r++) {
        float a = u;
        const float4* ip = (const float4*)(sIn + r * 64);
        #pragma unroll
        for (int j = 0; j < 16; j++) {
            float4 x = ip[j];
            a += m[j].x * x.x + m[j].y * x.y + m[j].z * x.z + m[j].w * x.w;
        }
        accs[r] = a;
        sRed[r * 128 + g] = c1 * a;
    }

    float* dst = (isV ? g_vvT : g_wT) + b * 32768 + g * 256 + x0;
    #pragma unroll
    for (int r4 = 0; r4 < 4; r4++)
        *(float4*)(dst + r4 * 4) = make_float4(accs[r4*4], accs[r4*4+1], accs[r4*4+2], accs[r4*4+3]);

    __syncthreads();
    int ww = g >> 5, lane = g & 31;
    #pragma unroll
    for (int rr = 0; rr < 4; rr++) {
        int row = ww * 4 + rr;
        float4 xx = ((const float4*)(sRed + row * 128))[lane];
        float s = xx.x + xx.y + xx.z + xx.w;
        #pragma unroll
        for (int off = 16; off; off >>= 1) s += __shfl_xor_sync(0xffffffffu, s, off);
        if (lane == 0) g_PQ[rbase + row] = s;
    }
}

// ============================================================
// K3: A tile kernel, packed f32x2.
// ============================================================
__global__ void __launch_bounds__(256) k_a(const float* __restrict__ ba2p,
                                           float* __restrict__ out)
{
    extern __shared__ float sm[];
    float* sVd = sm;            // 128*128
    float* sW  = sm + 16384;    // 128*64
    float* sC2 = sm + 24576;    // 256
    float* sP  = sm + 24832;    // 64
    float* sQ  = sm + 24896;    // 64
    const int b = blockIdx.z, oc = blockIdx.y, ic = blockIdx.x;
    const int tid = threadIdx.x;

    const float* vsrc = g_vvT + b * 32768 + oc * 64;
    const float* wsrc = g_wT  + b * 32768 + ic * 64;
    #pragma unroll
    for (int l = tid; l < 2048; l += 256) {
        int gg = l >> 4, q = (l & 15) << 2;
        float4 wv = *(const float4*)(wsrc + gg * 256 + q);
        *(float4*)(sW + gg * 64 + q) = wv;
        float4 vv = *(const float4*)(vsrc + gg * 256 + q);
        float* vd = sVd + gg * 128 + q * 2;
        ((float4*)vd)[0] = make_float4(vv.x, vv.x, vv.y, vv.y);
        ((float4*)vd)[1] = make_float4(vv.z, vv.z, vv.w, vv.w);
    }
    sC2[tid] = g_c2d[tid & 255];
    if (tid < 64)       sP[tid] = g_PQ[b * 256 + oc * 64 + tid];
    else if (tid < 128) sQ[tid - 64] = g_PQ[2048 + b * 256 + ic * 64 + (tid - 64)];
    __syncthreads();

    const int tx = tid & 15, ty = tid >> 4;
    unsigned long long a00 = 0, a01 = 0, a10 = 0, a11 = 0,
                       a20 = 0, a21 = 0, a30 = 0, a31 = 0;
    const float* vbase = sVd + ty * 8;
    const float* wbase = sW + tx * 4;
    const unsigned long long* c2base = (const unsigned long long*)sC2;
    const unsigned long long MASK = 0x7FFFFFFF7FFFFFFFULL;

    #pragma unroll 4
    for (int gg = 0; gg < 128; gg++) {
        ulonglong2 vp01 = *(const ulonglong2*)(vbase + gg * 128);
        ulonglong2 vp23 = *(const ulonglong2*)(vbase + gg * 128 + 4);
        ulonglong2 wp   = *(const ulonglong2*)(wbase + gg * 64);
        unsigned long long c2 = c2base[gg];
        unsigned long long t;
        t = addp(vp01.x, wp.x) & MASK;  a00 = fmap(c2, t, a00);
        t = addp(vp01.x, wp.y) & MASK;  a01 = fmap(c2, t, a01);
        t = addp(vp01.y, wp.x) & MASK;  a10 = fmap(c2, t, a10);
        t = addp(vp01.y, wp.y) & MASK;  a11 = fmap(c2, t, a11);
        t = addp(vp23.x, wp.x) & MASK;  a20 = fmap(c2, t, a20);
        t = addp(vp23.x, wp.y) & MASK;  a21 = fmap(c2, t, a21);
        t = addp(vp23.y, wp.x) & MASK;  a30 = fmap(c2, t, a30);
        t = addp(vp23.y, wp.y) & MASK;  a31 = fmap(c2, t, a31);
    }

    const float ba2v = ba2p[0];
    float4 q4 = *(const float4*)(sQ + tx * 4);
    unsigned long long acc[4][2] = {{a00,a01},{a10,a11},{a20,a21},{a30,a31}};
    #pragma unroll
    for (int r = 0; r < 4; r++) {
        float pr = sP[ty * 4 + r] + ba2v;
        float4 res;
        res.x = __uint_as_float((unsigned)(acc[r][0] & 0xffffffffULL)) + pr + q4.x;
        res.y = __uint_as_float((unsigned)(acc[r][0] >> 32))           + pr + q4.y;
        res.z = __uint_as_float((unsigned)(acc[r][1] & 0xffffffffULL)) + pr + q4.z;
        res.w = __uint_as_float((unsigned)(acc[r][1] >> 32))           + pr + q4.w;
        int og = oc * 64 + ty * 4 + r;
        *(float4*)(out + OFF_A + b * 65536 + og * 256 + ic * 64 + tx * 4) = res;
    }
}

// ============================================================
extern "C" void kernel_launch(void* const* d_in, const int* in_sizes, int n_in,
                              void* d_out, int out_size)
{
    const float* ope   = (const float*)d_in[0];
    const float* ins   = (const float*)d_in[1];
    const float* h_in  = (const float*)d_in[2];
    const float* c_in  = (const float*)d_in[3];
    const float* W_ih  = (const float*)d_in[4];
    const float* W_hh  = (const float*)d_in[5];
    const float* b_ih  = (const float*)d_in[6];
    const float* b_hh  = (const float*)d_in[7];
    const float* Wv0   = (const float*)d_in[8];
    const float* bv0   = (const float*)d_in[9];
    const float* Wv1   = (const float*)d_in[10];
    const float* bv1   = (const float*)d_in[11];
    const float* Wv2   = (const float*)d_in[12];
    const float* bv2   = (const float*)d_in[13];
    const float* Wa0   = (const float*)d_in[14];
    const float* ba0   = (const float*)d_in[15];
    const float* Wa1   = (const float*)d_in[16];
    const float* ba1   = (const float*)d_in[17];
    const float* Wa2   = (const float*)d_in[18];
    const float* ba2   = (const float*)d_in[19];
    float* out = (float*)d_out;

    cudaFuncSetAttribute(k_a, cudaFuncAttributeMaxDynamicSharedMemorySize, 99840);

    k_setup<<<25, 256>>>(ope, h_in, c_in, W_ih, W_hh, b_ih, b_hh,
                         Wv0, bv0, Wv1, bv1, Wv2, bv2, Wa0, ba0, Wa1, ba1, Wa2, out);
    k_vw<<<256, 128>>>(ope, ins);
    k_a<<<dim3(4, 4, 8), 256, 99840>>>(ba2, out);
}

// round 5
// speedup vs baseline: 2.5636x; 1.1953x over previous
#include <cuda_runtime.h>
#include <math.h>

// B=8, D=64, O=256, I=256, G=128
// Output: V(8) | A(8*65536) | hn(8*64) | cn(8*64)
#define OFF_V  0
#define OFF_A  8
#define OFF_HN 524296
#define OFF_CN 524808

// ---- scratch ----
__device__ float g_u[8 * 128];
__device__ float g_M[2 * 128 * 64];
__device__ float g_c1[128];
__device__ float g_c2d[256];
__device__ float g_vvT[8 * 128 * 256];  // [b][g][o]
__device__ float g_wT[8 * 128 * 256];   // [b][g][i]
__device__ float g_PQ[4096];

__device__ __forceinline__ float sigm(float x) { return 1.0f / (1.0f + expf(-x)); }

__device__ __forceinline__ float warp_sum(float v) {
    #pragma unroll
    for (int o = 16; o; o >>= 1) v += __shfl_xor_sync(0xffffffffu, v, o);
    return v;
}

__device__ __forceinline__ unsigned long long addp(unsigned long long a, unsigned long long b) {
    unsigned long long r;
    asm("add.rn.f32x2 %0, %1, %2;" : "=l"(r) : "l"(a), "l"(b));
    return r;
}
__device__ __forceinline__ unsigned long long fmap(unsigned long long a, unsigned long long b, unsigned long long c) {
    unsigned long long r;
    asm("fma.rn.f32x2 %0, %1, %2, %3;" : "=l"(r) : "l"(a), "l"(b), "l"(c));
    return r;
}

// ============================================================
// K1: fused setup.
//   blocks 0..15 : M = Wa1@[Wo|Wi]  (smem-staged mini-GEMM)
//   block  16    : c1 / c2d
//   blocks 17..24: per-batch mean / LSTM / V-head / u
//                  (stage weights -> smem, thread-per-row, no shuffles)
// dynamic smem: 256*132 floats = 135168 B weight buffer
// ============================================================
__global__ void __launch_bounds__(256) k_setup(
                        const float* __restrict__ ope,
                        const float* __restrict__ h_in,
                        const float* __restrict__ c_in,
                        const float* __restrict__ W_ih,
                        const float* __restrict__ W_hh,
                        const float* __restrict__ b_ih,
                        const float* __restrict__ b_hh,
                        const float* __restrict__ Wv0, const float* __restrict__ bv0,
                        const float* __restrict__ Wv1, const float* __restrict__ bv1,
                        const float* __restrict__ Wv2, const float* __restrict__ bv2,
                        const float* __restrict__ Wa0, const float* __restrict__ ba0,
                        const float* __restrict__ Wa1, const float* __restrict__ ba1,
                        const float* __restrict__ Wa2,
                        float* __restrict__ out)
{
    const int t = threadIdx.x;

    if (blockIdx.x < 16) {
        // ---- M-part: block -> (m, 16-row g chunk) ----
        __shared__ __align__(16) float sA[16 * 129];
        __shared__ __align__(16) float sB[128 * 72];
        const int m  = blockIdx.x >> 3;
        const int gc = blockIdx.x & 7;

        #pragma unroll
        for (int i = 0; i < 8; i++) {
            int idx = t + i * 256;
            sA[(idx >> 7) * 129 + (idx & 127)] = Wa1[gc * 2048 + idx];
        }
        {
            int hh0 = t >> 4, c4 = t & 15;
            #pragma unroll
            for (int i = 0; i < 8; i++) {
                int hh = hh0 + i * 16;
                float4 v = *(const float4*)(Wa0 + hh * 192 + 64 + m * 64 + c4 * 4);
                *(float4*)(sB + hh * 72 + c4 * 4) = v;
            }
        }
        __syncthreads();

        const int g = t >> 4, dg = t & 15;
        float4 acc = make_float4(0.f, 0.f, 0.f, 0.f);
        const float* arow = sA + g * 129;
        const float* bcol = sB + dg * 4;
        #pragma unroll 8
        for (int hh = 0; hh < 128; hh++) {
            float a = arow[hh];
            float4 bv = *(const float4*)(bcol + hh * 72);
            acc.x += a * bv.x; acc.y += a * bv.y; acc.z += a * bv.z; acc.w += a * bv.w;
        }
        *(float4*)(g_M + m * 8192 + (gc * 16 + g) * 64 + dg * 4) = acc;
        return;
    }

    if (blockIdx.x == 16) {
        if (t < 128) {
            float w2 = Wa2[t];
            g_c1[t] = 0.505f * w2;
            g_c2d[2 * t]     = 0.495f * w2;
            g_c2d[2 * t + 1] = 0.495f * w2;
        }
        return;
    }

    // ---- small part ----
    extern __shared__ float dsm[];          // [256][132] weight buffer
    __shared__ float sPart[1024];
    __shared__ float s_x[128];              // [state ; h]
    __shared__ float s_gates[256], s_hn[64];
    __shared__ float s_z0[128], s_t[128], s_z1[128];
    const int b = blockIdx.x - 17;

    // Stage 1: gates weights -> dsm rows: [W_ih row | W_hh row]
    #pragma unroll
    for (int i = 0; i < 16; i++) {
        int l = t + i * 256;                // 0..4095
        int r = l >> 4, q = l & 15;
        float4 a = *(const float4*)(W_ih + r * 64 + q * 4);
        *(float4*)(dsm + r * 132 + q * 4) = a;
        float4 bb = *(const float4*)(W_hh + r * 64 + q * 4);
        *(float4*)(dsm + r * 132 + 64 + q * 4) = bb;
    }
    if (t >= 64 && t < 128) s_x[t] = h_in[b * 64 + (t - 64)];

    // mean over 256 ope rows: coalesced float4 loads
    {
        int dq = t & 15, rc = t >> 4;
        const float* base = ope + (b * 258 + 1 + rc * 16) * 64 + dq * 4;
        float4 s = make_float4(0.f, 0.f, 0.f, 0.f);
        #pragma unroll
        for (int rr = 0; rr < 16; rr++) {
            float4 x = *(const float4*)(base + rr * 64);
            s.x += x.x; s.y += x.y; s.z += x.z; s.w += x.w;
        }
        *(float4*)(sPart + rc * 64 + dq * 4) = s;
    }
    __syncthreads();
    if (t < 64) {
        float s = 0.f;
        #pragma unroll
        for (int rc = 0; rc < 16; rc++) s += sPart[rc * 64 + t];
        s_x[t] = s * (1.0f / 256.0f);
    }
    __syncthreads();

    // gates: thread t = row t, K=128 from dsm + broadcast s_x
    {
        float acc = b_ih[t] + b_hh[t];
        const float4* wr = (const float4*)(dsm + t * 132);
        #pragma unroll
        for (int j = 0; j < 32; j++) {
            float4 w4 = wr[j];
            float4 x4 = *(const float4*)(s_x + j * 4);
            acc += w4.x * x4.x + w4.y * x4.y + w4.z * x4.z + w4.w * x4.w;
        }
        s_gates[t] = acc;
    }
    __syncthreads();

    // LSTM cell (t<64) ; meanwhile all threads stage layer-2 weights
    if (t < 64) {
        float ig = sigm(s_gates[t]);
        float fg = sigm(s_gates[64 + t]);
        float gg = tanhf(s_gates[128 + t]);
        float og = sigm(s_gates[192 + t]);
        float cn = fg * c_in[b * 64 + t] + ig * gg;
        float hn = og * tanhf(cn);
        s_hn[t] = hn;
        out[OFF_HN + b * 64 + t] = hn;
        out[OFF_CN + b * 64 + t] = cn;
    }
    // stage 2: rows 0-127 = Wv0, rows 128-255 = Wa0[:, :64]
    #pragma unroll
    for (int i = 0; i < 16; i++) {
        int l = t + i * 256;                // 0..4095
        int r = l >> 4, q = l & 15;
        float4 v = (r < 128) ? *(const float4*)(Wv0 + r * 64 + q * 4)
                             : *(const float4*)(Wa0 + (r - 128) * 192 + q * 4);
        *(float4*)(dsm + r * 132 + q * 4) = v;
    }
    __syncthreads();

    // layer 2: thread t = row t, K=64, x = s_hn
    {
        float acc = (t < 128) ? bv0[t] : ba0[t - 128];
        const float4* wr = (const float4*)(dsm + t * 132);
        #pragma unroll
        for (int j = 0; j < 16; j++) {
            float4 w4 = wr[j];
            float4 x4 = *(const float4*)(s_hn + j * 4);
            acc += w4.x * x4.x + w4.y * x4.y + w4.z * x4.z + w4.w * x4.w;
        }
        if (t < 128) s_z0[t] = acc;
        else         s_t[t - 128] = acc;
    }
    __syncthreads();

    // stage 3: rows 0-127 = Wv1, rows 128-255 = Wa1
    #pragma unroll
    for (int i = 0; i < 32; i++) {
        int l = t + i * 256;                // 0..8191
        int r = l >> 5, q = l & 31;
        float4 v = (r < 128) ? *(const float4*)(Wv1 + r * 128 + q * 4)
                             : *(const float4*)(Wa1 + (r - 128) * 128 + q * 4);
        *(float4*)(dsm + r * 132 + q * 4) = v;
    }
    __syncthreads();

    // layer 3: thread t = row t, K=128; warps 0-3 x=s_z0, warps 4-7 x=s_t
    {
        const float* xv = (t < 128) ? s_z0 : s_t;
        float acc = (t < 128) ? bv1[t] : ba1[t - 128];
        const float4* wr = (const float4*)(dsm + t * 132);
        #pragma unroll
        for (int j = 0; j < 32; j++) {
            float4 w4 = wr[j];
            float4 x4 = *(const float4*)(xv + j * 4);
            acc += w4.x * x4.x + w4.y * x4.y + w4.z * x4.z + w4.w * x4.w;
        }
        if (t < 128) s_z1[t] = (acc >= 0.f) ? acc : 0.01f * acc;
        else         g_u[b * 128 + (t - 128)] = acc;
    }
    __syncthreads();

    if (t < 32) {
        float4 x = *(const float4*)(s_z1 + t * 4);
        float4 ww = *(const float4*)(Wv2 + t * 4);
        float acc = ww.x * x.x + ww.y * x.y + ww.z * x.z + ww.w * x.w;
        acc = warp_sum(acc);
        if (t == 0) out[OFF_V + b] = acc + bv2[0];
    }
}

// ============================================================
// K2: vv/w rows (transposed output [b][g][x]) + fused P/Q.
// ============================================================
__global__ void __launch_bounds__(128) k_vw(const float* __restrict__ ope,
                                            const float* __restrict__ ins)
{
    __shared__ float sIn[1024];
    __shared__ float sRed[2048];
    const int rbase = blockIdx.x * 16;
    const int g = threadIdx.x;
    const bool isV = (rbase < 2048);
    const int rb = isV ? rbase : (rbase - 2048);
    const int b = rb >> 8;
    const int x0 = rb & 255;

    const float4* Mrow = (const float4*)(g_M + (isV ? 0 : 8192) + g * 64);
    float4 m[16];
    #pragma unroll
    for (int j = 0; j < 16; j++) m[j] = Mrow[j];

    const float4* s4 = (const float4*)(isV ? (ope + (b * 258 + 1 + x0) * 64)
                                           : (ins + (b * 256 + x0) * 64));
    ((float4*)sIn)[g] = s4[g];
    ((float4*)sIn)[g + 128] = s4[g + 128];

    const float u = isV ? g_u[b * 128 + g] : 0.0f;
    const float c1 = g_c1[g];
    __syncthreads();

    float accs[16];
    #pragma unroll
    for (int r = 0; r < 16; r++) {
        float a = u;
        const float4* ip = (const float4*)(sIn + r * 64);
        #pragma unroll
        for (int j = 0; j < 16; j++) {
            float4 x = ip[j];
            a += m[j].x * x.x + m[j].y * x.y + m[j].z * x.z + m[j].w * x.w;
        }
        accs[r] = a;
        sRed[r * 128 + g] = c1 * a;
    }

    float* dst = (isV ? g_vvT : g_wT) + b * 32768 + g * 256 + x0;
    #pragma unroll
    for (int r4 = 0; r4 < 4; r4++)
        *(float4*)(dst + r4 * 4) = make_float4(accs[r4*4], accs[r4*4+1], accs[r4*4+2], accs[r4*4+3]);

    __syncthreads();
    int ww = g >> 5, lane = g & 31;
    #pragma unroll
    for (int rr = 0; rr < 4; rr++) {
        int row = ww * 4 + rr;
        float4 xx = ((const float4*)(sRed + row * 128))[lane];
        float s = xx.x + xx.y + xx.z + xx.w;
        #pragma unroll
        for (int off = 16; off; off >>= 1) s += __shfl_xor_sync(0xffffffffu, s, off);
        if (lane == 0) g_PQ[rbase + row] = s;
    }
}

// ============================================================
// K3: A tile kernel, packed f32x2.
// ============================================================
__global__ void __launch_bounds__(256) k_a(const float* __restrict__ ba2p,
                                           float* __restrict__ out)
{
    extern __shared__ float sm[];
    float* sVd = sm;            // 128*128
    float* sW  = sm + 16384;    // 128*64
    float* sC2 = sm + 24576;    // 256
    float* sP  = sm + 24832;    // 64
    float* sQ  = sm + 24896;    // 64
    const int b = blockIdx.z, oc = blockIdx.y, ic = blockIdx.x;
    const int tid = threadIdx.x;

    const float* vsrc = g_vvT + b * 32768 + oc * 64;
    const float* wsrc = g_wT  + b * 32768 + ic * 64;
    #pragma unroll
    for (int l = tid; l < 2048; l += 256) {
        int gg = l >> 4, q = (l & 15) << 2;
        float4 wv = *(const float4*)(wsrc + gg * 256 + q);
        *(float4*)(sW + gg * 64 + q) = wv;
        float4 vv = *(const float4*)(vsrc + gg * 256 + q);
        float* vd = sVd + gg * 128 + q * 2;
        ((float4*)vd)[0] = make_float4(vv.x, vv.x, vv.y, vv.y);
        ((float4*)vd)[1] = make_float4(vv.z, vv.z, vv.w, vv.w);
    }
    sC2[tid] = g_c2d[tid & 255];
    if (tid < 64)       sP[tid] = g_PQ[b * 256 + oc * 64 + tid];
    else if (tid < 128) sQ[tid - 64] = g_PQ[2048 + b * 256 + ic * 64 + (tid - 64)];
    __syncthreads();

    const int tx = tid & 15, ty = tid >> 4;
    unsigned long long a00 = 0, a01 = 0, a10 = 0, a11 = 0,
                       a20 = 0, a21 = 0, a30 = 0, a31 = 0;
    const float* vbase = sVd + ty * 8;
    const float* wbase = sW + tx * 4;
    const unsigned long long* c2base = (const unsigned long long*)sC2;
    const unsigned long long MASK = 0x7FFFFFFF7FFFFFFFULL;

    #pragma unroll 4
    for (int gg = 0; gg < 128; gg++) {
        ulonglong2 vp01 = *(const ulonglong2*)(vbase + gg * 128);
        ulonglong2 vp23 = *(const ulonglong2*)(vbase + gg * 128 + 4);
        ulonglong2 wp   = *(const ulonglong2*)(wbase + gg * 64);
        unsigned long long c2 = c2base[gg];
        unsigned long long t;
        t = addp(vp01.x, wp.x) & MASK;  a00 = fmap(c2, t, a00);
        t = addp(vp01.x, wp.y) & MASK;  a01 = fmap(c2, t, a01);
        t = addp(vp01.y, wp.x) & MASK;  a10 = fmap(c2, t, a10);
        t = addp(vp01.y, wp.y) & MASK;  a11 = fmap(c2, t, a11);
        t = addp(vp23.x, wp.x) & MASK;  a20 = fmap(c2, t, a20);
        t = addp(vp23.x, wp.y) & MASK;  a21 = fmap(c2, t, a21);
        t = addp(vp23.y, wp.x) & MASK;  a30 = fmap(c2, t, a30);
        t = addp(vp23.y, wp.y) & MASK;  a31 = fmap(c2, t, a31);
    }

    const float ba2v = ba2p[0];
    float4 q4 = *(const float4*)(sQ + tx * 4);
    unsigned long long acc[4][2] = {{a00,a01},{a10,a11},{a20,a21},{a30,a31}};
    #pragma unroll
    for (int r = 0; r < 4; r++) {
        float pr = sP[ty * 4 + r] + ba2v;
        float4 res;
        res.x = __uint_as_float((unsigned)(acc[r][0] & 0xffffffffULL)) + pr + q4.x;
        res.y = __uint_as_float((unsigned)(acc[r][0] >> 32))           + pr + q4.y;
        res.z = __uint_as_float((unsigned)(acc[r][1] & 0xffffffffULL)) + pr + q4.z;
        res.w = __uint_as_float((unsigned)(acc[r][1] >> 32))           + pr + q4.w;
        int og = oc * 64 + ty * 4 + r;
        *(float4*)(out + OFF_A + b * 65536 + og * 256 + ic * 64 + tx * 4) = res;
    }
}

// ============================================================
extern "C" void kernel_launch(void* const* d_in, const int* in_sizes, int n_in,
                              void* d_out, int out_size)
{
    const float* ope   = (const float*)d_in[0];
    const float* ins   = (const float*)d_in[1];
    const float* h_in  = (const float*)d_in[2];
    const float* c_in  = (const float*)d_in[3];
    const float* W_ih  = (const float*)d_in[4];
    const float* W_hh  = (const float*)d_in[5];
    const float* b_ih  = (const float*)d_in[6];
    const float* b_hh  = (const float*)d_in[7];
    const float* Wv0   = (const float*)d_in[8];
    const float* bv0   = (const float*)d_in[9];
    const float* Wv1   = (const float*)d_in[10];
    const float* bv1   = (const float*)d_in[11];
    const float* Wv2   = (const float*)d_in[12];
    const float* bv2   = (const float*)d_in[13];
    const float* Wa0   = (const float*)d_in[14];
    const float* ba0   = (const float*)d_in[15];
    const float* Wa1   = (const float*)d_in[16];
    const float* ba1   = (const float*)d_in[17];
    const float* Wa2   = (const float*)d_in[18];
    const float* ba2   = (const float*)d_in[19];
    float* out = (float*)d_out;

    cudaFuncSetAttribute(k_setup, cudaFuncAttributeMaxDynamicSharedMemorySize, 135168);
    cudaFuncSetAttribute(k_a, cudaFuncAttributeMaxDynamicSharedMemorySize, 99840);

    k_setup<<<25, 256, 135168>>>(ope, h_in, c_in, W_ih, W_hh, b_ih, b_hh,
                                 Wv0, bv0, Wv1, bv1, Wv2, bv2, Wa0, ba0, Wa1, ba1, Wa2, out);
    k_vw<<<256, 128>>>(ope, ins);
    k_a<<<dim3(4, 4, 8), 256, 99840>>>(ba2, out);
}

// round 6
// speedup vs baseline: 2.7421x; 1.0696x over previous
#include <cuda_runtime.h>
#include <math.h>

// B=8, D=64, O=256, I=256, G=128
// Output: V(8) | A(8*65536) | hn(8*64) | cn(8*64)
#define OFF_V  0
#define OFF_A  8
#define OFF_HN 524296
#define OFF_CN 524808

// ---- scratch ----
__device__ float g_hn[8 * 64];
__device__ float g_u[8 * 128];
__device__ float g_pc[8];
__device__ float g_M[4 * 128 * 64];     // m0=Wa1@Wo, m1=Wa1@Wi, m2=Wa1@Ws, m3=Wv1@Wv0
__device__ float g_bba[128];            // Wa1@ba0 + ba1
__device__ float g_bbv[128];            // Wv1@bv0 + bv1
__device__ float g_c1[128];
__device__ float g_c2d[256];
__device__ float g_vvT[8 * 128 * 256];  // [b][g][o]  (u NOT included)
__device__ float g_wT[8 * 128 * 256];   // [b][g][i]
__device__ float g_PQ[4096];            // P' (no u-term) and Q

__device__ __forceinline__ float sigm(float x) { return 1.0f / (1.0f + expf(-x)); }

__device__ __forceinline__ float warp_sum(float v) {
    #pragma unroll
    for (int o = 16; o; o >>= 1) v += __shfl_xor_sync(0xffffffffu, v, o);
    return v;
}

__device__ __forceinline__ unsigned long long addp(unsigned long long a, unsigned long long b) {
    unsigned long long r;
    asm("add.rn.f32x2 %0, %1, %2;" : "=l"(r) : "l"(a), "l"(b));
    return r;
}
__device__ __forceinline__ unsigned long long fmap(unsigned long long a, unsigned long long b, unsigned long long c) {
    unsigned long long r;
    asm("fma.rn.f32x2 %0, %1, %2, %3;" : "=l"(r) : "l"(a), "l"(b), "l"(c));
    return r;
}

// ============================================================
// K1: blocks 0..31 : 4 GEMMs (Wa1@Wo, Wa1@Wi, Wa1@Ws, Wv1@Wv0)
//     block  32    : fused biases + c1/c2d
//     blocks 33..40: per-batch mean / gates / LSTM -> g_hn, out
// dynamic smem 135168 B
// ============================================================
__global__ void __launch_bounds__(256) k_setup(
                        const float* __restrict__ ope,
                        const float* __restrict__ h_in,
                        const float* __restrict__ c_in,
                        const float* __restrict__ W_ih,
                        const float* __restrict__ W_hh,
                        const float* __restrict__ b_ih,
                        const float* __restrict__ b_hh,
                        const float* __restrict__ Wv0, const float* __restrict__ bv0,
                        const float* __restrict__ Wv1, const float* __restrict__ bv1,
                        const float* __restrict__ Wa0, const float* __restrict__ ba0,
                        const float* __restrict__ Wa1, const float* __restrict__ ba1,
                        const float* __restrict__ Wa2,
                        float* __restrict__ out)
{
    extern __shared__ float dsm[];
    const int t = threadIdx.x;

    if (blockIdx.x < 32) {
        // ---- GEMM part: block -> (m, 16-row g chunk) ----
        float* sA = dsm;                 // 16*129
        float* sB = dsm + 16 * 129;      // 128*72
        const int m  = blockIdx.x >> 3;  // 0..3
        const int gc = blockIdx.x & 7;

        const float* Aglob = (m == 3) ? Wv1 : Wa1;
        #pragma unroll
        for (int i = 0; i < 8; i++) {
            int idx = t + i * 256;
            sA[(idx >> 7) * 129 + (idx & 127)] = Aglob[gc * 2048 + idx];
        }
        {
            int hh0 = t >> 4, c4 = t & 15;
            #pragma unroll
            for (int i = 0; i < 8; i++) {
                int hh = hh0 + i * 16;
                const float* src = (m == 3) ? (Wv0 + hh * 64)
                                            : (Wa0 + hh * 192 + ((m == 0) ? 64 : (m == 1) ? 128 : 0));
                float4 v = *(const float4*)(src + c4 * 4);
                *(float4*)(sB + hh * 72 + c4 * 4) = v;
            }
        }
        __syncthreads();

        const int g = t >> 4, dg = t & 15;
        float4 acc = make_float4(0.f, 0.f, 0.f, 0.f);
        const float* arow = sA + g * 129;
        const float* bcol = sB + dg * 4;
        #pragma unroll 8
        for (int hh = 0; hh < 128; hh++) {
            float a = arow[hh];
            float4 bv = *(const float4*)(bcol + hh * 72);
            acc.x += a * bv.x; acc.y += a * bv.y; acc.z += a * bv.z; acc.w += a * bv.w;
        }
        *(float4*)(g_M + m * 8192 + (gc * 16 + g) * 64 + dg * 4) = acc;
        return;
    }

    if (blockIdx.x == 32) {
        // biases: bba = Wa1@ba0 + ba1 ; bbv = Wv1@bv0 + bv1 ; c1/c2d
        __shared__ float sb[256];    // [ba0 | bv0]
        if (t < 128) sb[t] = ba0[t];
        else         sb[t] = bv0[t - 128];
        __syncthreads();
        if (t < 128) {
            float acc = ba1[t];
            const float4* row = (const float4*)(Wa1 + t * 128);
            #pragma unroll 8
            for (int j = 0; j < 32; j++) {
                float4 w4 = row[j];
                float4 x4 = *(const float4*)(sb + j * 4);
                acc += w4.x * x4.x + w4.y * x4.y + w4.z * x4.z + w4.w * x4.w;
            }
            g_bba[t] = acc;
            float w2 = Wa2[t];
            g_c1[t] = 0.505f * w2;
            g_c2d[2 * t]     = 0.495f * w2;
            g_c2d[2 * t + 1] = 0.495f * w2;
        } else {
            int r = t - 128;
            float acc = bv1[r];
            const float4* row = (const float4*)(Wv1 + r * 128);
            #pragma unroll 8
            for (int j = 0; j < 32; j++) {
                float4 w4 = row[j];
                float4 x4 = *(const float4*)(sb + 128 + j * 4);
                acc += w4.x * x4.x + w4.y * x4.y + w4.z * x4.z + w4.w * x4.w;
            }
            g_bbv[r] = acc;
        }
        return;
    }

    // ---- small part: mean -> gates -> LSTM -> g_hn ----
    __shared__ float sPart[1024];
    __shared__ float s_x[128];
    __shared__ float s_gates[256];
    const int b = blockIdx.x - 33;

    // stage [W_ih | W_hh] rows into dsm (concurrent with mean loads)
    #pragma unroll
    for (int i = 0; i < 16; i++) {
        int l = t + i * 256;
        int r = l >> 4, q = l & 15;
        float4 a = *(const float4*)(W_ih + r * 64 + q * 4);
        *(float4*)(dsm + r * 132 + q * 4) = a;
        float4 bb = *(const float4*)(W_hh + r * 64 + q * 4);
        *(float4*)(dsm + r * 132 + 64 + q * 4) = bb;
    }
    if (t >= 64 && t < 128) s_x[t] = h_in[b * 64 + (t - 64)];

    {
        int dq = t & 15, rc = t >> 4;
        const float* base = ope + (b * 258 + 1 + rc * 16) * 64 + dq * 4;
        float4 s = make_float4(0.f, 0.f, 0.f, 0.f);
        #pragma unroll
        for (int rr = 0; rr < 16; rr++) {
            float4 x = *(const float4*)(base + rr * 64);
            s.x += x.x; s.y += x.y; s.z += x.z; s.w += x.w;
        }
        *(float4*)(sPart + rc * 64 + dq * 4) = s;
    }
    __syncthreads();
    if (t < 64) {
        float s = 0.f;
        #pragma unroll
        for (int rc = 0; rc < 16; rc++) s += sPart[rc * 64 + t];
        s_x[t] = s * (1.0f / 256.0f);
    }
    __syncthreads();

    {
        float acc = b_ih[t] + b_hh[t];
        const float4* wr = (const float4*)(dsm + t * 132);
        #pragma unroll
        for (int j = 0; j < 32; j++) {
            float4 w4 = wr[j];
            float4 x4 = *(const float4*)(s_x + j * 4);
            acc += w4.x * x4.x + w4.y * x4.y + w4.z * x4.z + w4.w * x4.w;
        }
        s_gates[t] = acc;
    }
    __syncthreads();

    if (t < 64) {
        float ig = sigm(s_gates[t]);
        float fg = sigm(s_gates[64 + t]);
        float gg = tanhf(s_gates[128 + t]);
        float og = sigm(s_gates[192 + t]);
        float cn = fg * c_in[b * 64 + t] + ig * gg;
        float hn = og * tanhf(cn);
        g_hn[b * 64 + t] = hn;
        out[OFF_HN + b * 64 + t] = hn;
        out[OFF_CN + b * 64 + t] = cn;
    }
}

// ============================================================
// K2: blocks 0..255: vv/w rows (transposed, NO u) + fused P'/Q.
//     blocks 256..263: u / pc / V per batch (from g_hn + precomputed).
// ============================================================
__global__ void __launch_bounds__(128) k_vw(const float* __restrict__ ope,
                                            const float* __restrict__ ins,
                                            const float* __restrict__ Wv2,
                                            const float* __restrict__ bv2,
                                            float* __restrict__ out)
{
    const int t = threadIdx.x;

    if (blockIdx.x >= 256) {
        // ---- u / pc / V block ----
        __shared__ float shn[64];
        __shared__ float spc[128];
        __shared__ float sz[128];
        const int b = blockIdx.x - 256;
        if (t < 64) shn[t] = g_hn[b * 64 + t];
        __syncthreads();

        // u row t
        {
            float acc = g_bba[t];
            const float4* row = (const float4*)(g_M + 2 * 8192 + t * 64);
            #pragma unroll
            for (int j = 0; j < 16; j++) {
                float4 w4 = row[j];
                float4 x4 = *(const float4*)(shn + j * 4);
                acc += w4.x * x4.x + w4.y * x4.y + w4.z * x4.z + w4.w * x4.w;
            }
            g_u[b * 128 + t] = acc;
            spc[t] = g_c1[t] * acc;
        }
        // z row t (V tower)
        {
            float acc = g_bbv[t];
            const float4* row = (const float4*)(g_M + 3 * 8192 + t * 64);
            #pragma unroll
            for (int j = 0; j < 16; j++) {
                float4 w4 = row[j];
                float4 x4 = *(const float4*)(shn + j * 4);
                acc += w4.x * x4.x + w4.y * x4.y + w4.z * x4.z + w4.w * x4.w;
            }
            sz[t] = (acc >= 0.f) ? acc : 0.01f * acc;
        }
        __syncthreads();
        int w = t >> 5, lane = t & 31;
        if (w == 0) {
            float4 x = *(const float4*)(spc + lane * 4);
            float s = x.x + x.y + x.z + x.w;
            s = warp_sum(s);
            if (lane == 0) g_pc[b] = s;
        } else if (w == 1) {
            float4 x = *(const float4*)(sz + lane * 4);
            float4 ww = *(const float4*)(Wv2 + lane * 4);
            float s = ww.x * x.x + ww.y * x.y + ww.z * x.z + ww.w * x.w;
            s = warp_sum(s);
            if (lane == 0) out[OFF_V + b] = s + bv2[0];
        }
        return;
    }

    __shared__ float sIn[1024];
    __shared__ float sRed[2048];
    const int rbase = blockIdx.x * 16;
    const int g = t;
    const bool isV = (rbase < 2048);
    const int rb = isV ? rbase : (rbase - 2048);
    const int b = rb >> 8;
    const int x0 = rb & 255;

    const float4* Mrow = (const float4*)(g_M + (isV ? 0 : 8192) + g * 64);
    float4 m[16];
    #pragma unroll
    for (int j = 0; j < 16; j++) m[j] = Mrow[j];

    const float4* s4 = (const float4*)(isV ? (ope + (b * 258 + 1 + x0) * 64)
                                           : (ins + (b * 256 + x0) * 64));
    ((float4*)sIn)[g] = s4[g];
    ((float4*)sIn)[g + 128] = s4[g + 128];

    const float c1 = g_c1[g];
    __syncthreads();

    float accs[16];
    #pragma unroll
    for (int r = 0; r < 16; r++) {
        float a = 0.f;
        const float4* ip = (const float4*)(sIn + r * 64);
        #pragma unroll
        for (int j = 0; j < 16; j++) {
            float4 x = ip[j];
            a += m[j].x * x.x + m[j].y * x.y + m[j].z * x.z + m[j].w * x.w;
        }
        accs[r] = a;
        sRed[r * 128 + g] = c1 * a;
    }

    float* dst = (isV ? g_vvT : g_wT) + b * 32768 + g * 256 + x0;
    #pragma unroll
    for (int r4 = 0; r4 < 4; r4++)
        *(float4*)(dst + r4 * 4) = make_float4(accs[r4*4], accs[r4*4+1], accs[r4*4+2], accs[r4*4+3]);

    __syncthreads();
    int ww = g >> 5, lane = g & 31;
    #pragma unroll
    for (int rr = 0; rr < 4; rr++) {
        int row = ww * 4 + rr;
        float4 xx = ((const float4*)(sRed + row * 128))[lane];
        float s = xx.x + xx.y + xx.z + xx.w;
        #pragma unroll
        for (int off = 16; off; off >>= 1) s += __shfl_xor_sync(0xffffffffu, s, off);
        if (lane == 0) g_PQ[rbase + row] = s;
    }
}

// ============================================================
// K3: A tile kernel, packed f32x2; u added at staging, pc in epilogue.
// ============================================================
__global__ void __launch_bounds__(256) k_a(const float* __restrict__ ba2p,
                                           float* __restrict__ out)
{
    extern __shared__ float sm[];
    float* sVd = sm;            // 128*128
    float* sW  = sm + 16384;    // 128*64
    float* sC2 = sm + 24576;    // 256
    float* sP  = sm + 24832;    // 64
    float* sQ  = sm + 24896;    // 64
    const int b = blockIdx.z, oc = blockIdx.y, ic = blockIdx.x;
    const int tid = threadIdx.x;

    const float pcb = g_pc[b] + ba2p[0];

    const float* vsrc = g_vvT + b * 32768 + oc * 64;
    const float* wsrc = g_wT  + b * 32768 + ic * 64;
    const float* usrc = g_u + b * 128;
    #pragma unroll
    for (int l = tid; l < 2048; l += 256) {
        int gg = l >> 4, q = (l & 15) << 2;
        float4 wv = *(const float4*)(wsrc + gg * 256 + q);
        *(float4*)(sW + gg * 64 + q) = wv;
        float uu = usrc[gg];
        float4 vv = *(const float4*)(vsrc + gg * 256 + q);
        vv.x += uu; vv.y += uu; vv.z += uu; vv.w += uu;
        float* vd = sVd + gg * 128 + q * 2;
        ((float4*)vd)[0] = make_float4(vv.x, vv.x, vv.y, vv.y);
        ((float4*)vd)[1] = make_float4(vv.z, vv.z, vv.w, vv.w);
    }
    sC2[tid] = g_c2d[tid & 255];
    if (tid < 64)       sP[tid] = g_PQ[b * 256 + oc * 64 + tid];
    else if (tid < 128) sQ[tid - 64] = g_PQ[2048 + b * 256 + ic * 64 + (tid - 64)];
    __syncthreads();

    const int tx = tid & 15, ty = tid >> 4;
    unsigned long long a00 = 0, a01 = 0, a10 = 0, a11 = 0,
                       a20 = 0, a21 = 0, a30 = 0, a31 = 0;
    const float* vbase = sVd + ty * 8;
    const float* wbase = sW + tx * 4;
    const unsigned long long* c2base = (const unsigned long long*)sC2;
    const unsigned long long MASK = 0x7FFFFFFF7FFFFFFFULL;

    #pragma unroll 4
    for (int gg = 0; gg < 128; gg++) {
        ulonglong2 vp01 = *(const ulonglong2*)(vbase + gg * 128);
        ulonglong2 vp23 = *(const ulonglong2*)(vbase + gg * 128 + 4);
        ulonglong2 wp   = *(const ulonglong2*)(wbase + gg * 64);
        unsigned long long c2 = c2base[gg];
        unsigned long long t;
        t = addp(vp01.x, wp.x) & MASK;  a00 = fmap(c2, t, a00);
        t = addp(vp01.x, wp.y) & MASK;  a01 = fmap(c2, t, a01);
        t = addp(vp01.y, wp.x) & MASK;  a10 = fmap(c2, t, a10);
        t = addp(vp01.y, wp.y) & MASK;  a11 = fmap(c2, t, a11);
        t = addp(vp23.x, wp.x) & MASK;  a20 = fmap(c2, t, a20);
        t = addp(vp23.x, wp.y) & MASK;  a21 = fmap(c2, t, a21);
        t = addp(vp23.y, wp.x) & MASK;  a30 = fmap(c2, t, a30);
        t = addp(vp23.y, wp.y) & MASK;  a31 = fmap(c2, t, a31);
    }

    float4 q4 = *(const float4*)(sQ + tx * 4);
    unsigned long long acc[4][2] = {{a00,a01},{a10,a11},{a20,a21},{a30,a31}};
    #pragma unroll
    for (int r = 0; r < 4; r++) {
        float pr = sP[ty * 4 + r] + pcb;
        float4 res;
        res.x = __uint_as_float((unsigned)(acc[r][0] & 0xffffffffULL)) + pr + q4.x;
        res.y = __uint_as_float((unsigned)(acc[r][0] >> 32))           + pr + q4.y;
        res.z = __uint_as_float((unsigned)(acc[r][1] & 0xffffffffULL)) + pr + q4.z;
        res.w = __uint_as_float((unsigned)(acc[r][1] >> 32))           + pr + q4.w;
        int og = oc * 64 + ty * 4 + r;
        *(float4*)(out + OFF_A + b * 65536 + og * 256 + ic * 64 + tx * 4) = res;
    }
}

// ============================================================
extern "C" void kernel_launch(void* const* d_in, const int* in_sizes, int n_in,
                              void* d_out, int out_size)
{
    const float* ope   = (const float*)d_in[0];
    const float* ins   = (const float*)d_in[1];
    const float* h_in  = (const float*)d_in[2];
    const float* c_in  = (const float*)d_in[3];
    const float* W_ih  = (const float*)d_in[4];
    const float* W_hh  = (const float*)d_in[5];
    const float* b_ih  = (const float*)d_in[6];
    const float* b_hh  = (const float*)d_in[7];
    const float* Wv0   = (const float*)d_in[8];
    const float* bv0   = (const float*)d_in[9];
    const float* Wv1   = (const float*)d_in[10];
    const float* bv1   = (const float*)d_in[11];
    const float* Wv2   = (const float*)d_in[12];
    const float* bv2   = (const float*)d_in[13];
    const float* Wa0   = (const float*)d_in[14];
    const float* ba0   = (const float*)d_in[15];
    const float* Wa1   = (const float*)d_in[16];
    const float* ba1   = (const float*)d_in[17];
    const float* Wa2   = (const float*)d_in[18];
    const float* ba2   = (const float*)d_in[19];
    float* out = (float*)d_out;

    cudaFuncSetAttribute(k_setup, cudaFuncAttributeMaxDynamicSharedMemorySize, 135168);
    cudaFuncSetAttribute(k_a, cudaFuncAttributeMaxDynamicSharedMemorySize, 99840);

    k_setup<<<41, 256, 135168>>>(ope, h_in, c_in, W_ih, W_hh, b_ih, b_hh,
                                 Wv0, bv0, Wv1, bv1, Wa0, ba0, Wa1, ba1, Wa2, out);
    k_vw<<<264, 128>>>(ope, ins, Wv2, bv2, out);
    k_a<<<dim3(4, 4, 8), 256, 99840>>>(ba2, out);
}